// round 2
// baseline (speedup 1.0000x reference)
#include <cuda_runtime.h>
#include <math.h>

#define SQ   2048
#define NB   2
#define NH   16
#define DKH  64
#define DM   1024
#define MROWS 4096   // NB*SQ

// Scratch (allocation-free rule: one __device__ global block)
// Layout: [0] Q  [1] K  [2] V  [3] A   each MROWS*DM floats (16 MB)
__device__ float g_scratch[4ull * MROWS * DM];

#define g_Q (g_scratch)
#define g_K (g_scratch + 1ull * MROWS * DM)
#define g_V (g_scratch + 2ull * MROWS * DM)
#define g_A (g_scratch + 3ull * MROWS * DM)

// ---------------------------------------------------------------------------
// Shared 128x128x(K=1024) fp32 GEMM mainloop. 256 threads, 8x8 per thread.
// A: row-major [4096 x 1024], B: row-major [1024 x 1024].
// ---------------------------------------------------------------------------
__device__ __forceinline__ void gemm_tile_1024(
    const float* __restrict__ A, const float* __restrict__ B,
    float acc[8][8], float (*As)[128], float (*Bs)[128],
    int by, int bx, int tid)
{
    const int arow = tid >> 1;          // 0..127
    const int acol = (tid & 1) << 2;    // 0 or 4
    const int brow = tid >> 5;          // 0..7
    const int bcol = (tid & 31) << 2;   // 0..124
    const int ty = tid >> 4, tx = tid & 15;

    const float* Ap = A + (size_t)(by * 128 + arow) * DM + acol;
    const float* Bp = B + (size_t)brow * DM + bx * 128 + bcol;

    for (int k0 = 0; k0 < DM; k0 += 8) {
        float4 av = *(const float4*)(Ap + k0);
        As[acol + 0][arow] = av.x;
        As[acol + 1][arow] = av.y;
        As[acol + 2][arow] = av.z;
        As[acol + 3][arow] = av.w;
        *(float4*)&Bs[brow][bcol] = *(const float4*)(Bp + (size_t)k0 * DM);
        __syncthreads();
#pragma unroll
        for (int kk = 0; kk < 8; kk++) {
            float a[8], b[8];
            *(float4*)&a[0] = *(const float4*)&As[kk][ty * 8];
            *(float4*)&a[4] = *(const float4*)&As[kk][ty * 8 + 4];
            *(float4*)&b[0] = *(const float4*)&Bs[kk][tx * 8];
            *(float4*)&b[4] = *(const float4*)&Bs[kk][tx * 8 + 4];
#pragma unroll
            for (int i = 0; i < 8; i++)
#pragma unroll
                for (int j = 0; j < 8; j++)
                    acc[i][j] = fmaf(a[i], b[j], acc[i][j]);
        }
        __syncthreads();
    }
}

// ---------------------------------------------------------------------------
// QKV projection: grid (8, 32, 3). z selects W/bias/output. Epilogue remaps
// [m=b*S+s][n=h*64+d] -> scratch layout [bh][s][d].
// ---------------------------------------------------------------------------
__global__ __launch_bounds__(256) void qkv_gemm(
    const float* __restrict__ x,
    const float* __restrict__ Wq, const float* __restrict__ bq,
    const float* __restrict__ Wk, const float* __restrict__ bk,
    const float* __restrict__ Wv, const float* __restrict__ bv)
{
    __shared__ float As[8][128];
    __shared__ float Bs[8][128];
    const float* W; const float* bias; float* C;
    if (blockIdx.z == 0)      { W = Wq; bias = bq; C = g_Q; }
    else if (blockIdx.z == 1) { W = Wk; bias = bk; C = g_K; }
    else                      { W = Wv; bias = bv; C = g_V; }

    float acc[8][8] = {};
    gemm_tile_1024(x, W, acc, As, Bs, blockIdx.y, blockIdx.x, threadIdx.x);

    const int ty = threadIdx.x >> 4, tx = threadIdx.x & 15;
#pragma unroll
    for (int i = 0; i < 8; i++) {
        int m = blockIdx.y * 128 + ty * 8 + i;
        int b = m >> 11, s = m & (SQ - 1);
#pragma unroll
        for (int j = 0; j < 8; j++) {
            int n = blockIdx.x * 128 + tx * 8 + j;
            int h = n >> 6, d = n & 63;
            C[(((size_t)(b * NH + h) * SQ + s) * DKH) + d] = acc[i][j] + bias[n];
        }
    }
}

// ---------------------------------------------------------------------------
// Output projection: out = g_A @ Wo + bo, plain row-major epilogue.
// ---------------------------------------------------------------------------
__global__ __launch_bounds__(256) void out_gemm(
    const float* __restrict__ Wo, const float* __restrict__ bo,
    float* __restrict__ out)
{
    __shared__ float As[8][128];
    __shared__ float Bs[8][128];
    float acc[8][8] = {};
    gemm_tile_1024(g_A, Wo, acc, As, Bs, blockIdx.y, blockIdx.x, threadIdx.x);

    const int ty = threadIdx.x >> 4, tx = threadIdx.x & 15;
#pragma unroll
    for (int i = 0; i < 8; i++) {
        int m = blockIdx.y * 128 + ty * 8 + i;
#pragma unroll
        for (int j = 0; j < 8; j++) {
            int n = blockIdx.x * 128 + tx * 8 + j;
            out[(size_t)m * DM + n] = acc[i][j] + bo[n];
        }
    }
}

// ---------------------------------------------------------------------------
// RoPE on g_Q and g_K in place. One thread per (buf, bh, s, j) pair, j<32.
// inv_freq computed in double for bit-consistency with the fp32 reference.
// ---------------------------------------------------------------------------
__global__ __launch_bounds__(256) void rope_kernel()
{
    int tid = blockIdx.x * blockDim.x + threadIdx.x;   // 0 .. 2^22-1
    int j  = tid & 31;
    int s  = (tid >> 5) & (SQ - 1);
    int bh = (tid >> 16) & 31;
    float* base = ((tid >> 21) ? g_K : g_Q) + ((size_t)(bh * SQ + s)) * DKH;

    float invf = (float)pow(10000.0, -(double)j / 32.0);
    float ang = (float)s * invf;
    float sn, c;
    sincosf(ang, &sn, &c);
    float x1 = base[j], x2 = base[j + 32];
    base[j]      = x1 * c - x2 * sn;
    base[j + 32] = x1 * sn + x2 * c;
}

// ---------------------------------------------------------------------------
// Flash attention, fp32, non-causal. Grid (S/64, B*H), 256 threads.
// Per CTA: 64 queries; loop over 32 key-tiles of 64.
// smem: Qt[d][q], Kt[d][k], Vs[k][d], Pt[k][q], all stride 68 (float4-aligned pad).
// Thread (ty,tx) = (tid/16, tid%16): scores micro-tile q=ty*4+i, k=tx*4+j;
// PV micro-tile q=ty*4+i, d=tx*4+j. Row stats live redundantly in the 16 tx lanes.
// ---------------------------------------------------------------------------
#define FA_STRIDE 68
#define FA_SMEM (4 * 64 * FA_STRIDE * 4)

__global__ __launch_bounds__(256) void flash_kernel()
{
    extern __shared__ float sm[];
    float* Qt = sm;                       // [64][68] (d-major)
    float* Kt = sm + 64 * FA_STRIDE;      // [64][68] (d-major)
    float* Vs = sm + 2 * 64 * FA_STRIDE;  // [64][68] (k-major)
    float* Pt = sm + 3 * 64 * FA_STRIDE;  // [64][68] (k-major)

    const int bh = blockIdx.y;
    const int qb = blockIdx.x;
    const int tid = threadIdx.x;
    const int ty = tid >> 4, tx = tid & 15;

    const float* Qg = g_Q + ((size_t)bh * SQ + qb * 64) * DKH;
    const float* Kg = g_K + (size_t)bh * SQ * DKH;
    const float* Vg = g_V + (size_t)bh * SQ * DKH;

    // Load Q tile (transposed, pre-scaled by 1/sqrt(64))
    for (int it = tid; it < 1024; it += 256) {
        int q = it >> 4, dv = (it & 15) << 2;
        float4 v = *(const float4*)(Qg + q * DKH + dv);
        Qt[(dv + 0) * FA_STRIDE + q] = v.x * 0.125f;
        Qt[(dv + 1) * FA_STRIDE + q] = v.y * 0.125f;
        Qt[(dv + 2) * FA_STRIDE + q] = v.z * 0.125f;
        Qt[(dv + 3) * FA_STRIDE + q] = v.w * 0.125f;
    }

    float m_i[4], l_i[4], o[4][4];
#pragma unroll
    for (int i = 0; i < 4; i++) {
        m_i[i] = -1e30f; l_i[i] = 0.f;
#pragma unroll
        for (int j = 0; j < 4; j++) o[i][j] = 0.f;
    }

    for (int kt = 0; kt < SQ / 64; kt++) {
        const float* Kp = Kg + kt * 64 * DKH;
        const float* Vp = Vg + kt * 64 * DKH;
        for (int it = tid; it < 1024; it += 256) {
            int r = it >> 4, dv = (it & 15) << 2;
            float4 kv = *(const float4*)(Kp + r * DKH + dv);
            Kt[(dv + 0) * FA_STRIDE + r] = kv.x;
            Kt[(dv + 1) * FA_STRIDE + r] = kv.y;
            Kt[(dv + 2) * FA_STRIDE + r] = kv.z;
            Kt[(dv + 3) * FA_STRIDE + r] = kv.w;
            *(float4*)&Vs[r * FA_STRIDE + dv] = *(const float4*)(Vp + r * DKH + dv);
        }
        __syncthreads();

        // S = Q K^T (scaled): 4x4 micro-tile per thread
        float sacc[4][4] = {};
#pragma unroll 4
        for (int d = 0; d < 64; d++) {
            float4 qv = *(const float4*)&Qt[d * FA_STRIDE + ty * 4];
            float4 kv = *(const float4*)&Kt[d * FA_STRIDE + tx * 4];
            float qa[4] = {qv.x, qv.y, qv.z, qv.w};
            float ka[4] = {kv.x, kv.y, kv.z, kv.w};
#pragma unroll
            for (int i = 0; i < 4; i++)
#pragma unroll
                for (int j = 0; j < 4; j++)
                    sacc[i][j] = fmaf(qa[i], ka[j], sacc[i][j]);
        }

        // Online softmax per query row (reduce across the 16 tx lanes)
#pragma unroll
        for (int i = 0; i < 4; i++) {
            float mx = fmaxf(fmaxf(sacc[i][0], sacc[i][1]),
                             fmaxf(sacc[i][2], sacc[i][3]));
#pragma unroll
            for (int off = 8; off >= 1; off >>= 1)
                mx = fmaxf(mx, __shfl_xor_sync(0xffffffffu, mx, off));
            float mnew = fmaxf(m_i[i], mx);
            float alpha = __expf(m_i[i] - mnew);
            float rs = 0.f;
#pragma unroll
            for (int jj = 0; jj < 4; jj++) {
                float p = __expf(sacc[i][jj] - mnew);
                Pt[(tx * 4 + jj) * FA_STRIDE + ty * 4 + i] = p;
                rs += p;
            }
#pragma unroll
            for (int off = 8; off >= 1; off >>= 1)
                rs += __shfl_xor_sync(0xffffffffu, rs, off);
            l_i[i] = l_i[i] * alpha + rs;
            m_i[i] = mnew;
#pragma unroll
            for (int jj = 0; jj < 4; jj++) o[i][jj] *= alpha;
        }
        __syncthreads();

        // O += P @ V: 4x4 micro-tile per thread (q=ty*4+i, d=tx*4+j)
#pragma unroll 4
        for (int k = 0; k < 64; k++) {
            float4 pv = *(const float4*)&Pt[k * FA_STRIDE + ty * 4];
            float4 vv = *(const float4*)&Vs[k * FA_STRIDE + tx * 4];
            float pa[4] = {pv.x, pv.y, pv.z, pv.w};
            float va[4] = {vv.x, vv.y, vv.z, vv.w};
#pragma unroll
            for (int i = 0; i < 4; i++)
#pragma unroll
                for (int j = 0; j < 4; j++)
                    o[i][j] = fmaf(pa[i], va[j], o[i][j]);
        }
        __syncthreads();
    }

    // Write attn output to [b][s][h*64+d]
    const int b = bh >> 4, h = bh & 15;
#pragma unroll
    for (int i = 0; i < 4; i++) {
        float inv_l = 1.f / l_i[i];
        int s = qb * 64 + ty * 4 + i;
#pragma unroll
        for (int j = 0; j < 4; j++) {
            g_A[((size_t)(b * SQ + s)) * DM + h * DKH + tx * 4 + j] = o[i][j] * inv_l;
        }
    }
}

// ---------------------------------------------------------------------------
extern "C" void kernel_launch(void* const* d_in, const int* in_sizes, int n_in,
                              void* d_out, int out_size)
{
    const float* x  = (const float*)d_in[0];
    const float* Wq = (const float*)d_in[1];
    const float* bq = (const float*)d_in[2];
    const float* Wk = (const float*)d_in[3];
    const float* bk = (const float*)d_in[4];
    const float* Wv = (const float*)d_in[5];
    const float* bv = (const float*)d_in[6];
    const float* Wo = (const float*)d_in[7];
    const float* bo = (const float*)d_in[8];
    float* out = (float*)d_out;

    // 1) QKV projections (remapped to [bh][s][d])
    qkv_gemm<<<dim3(8, 32, 3), 256>>>(x, Wq, bq, Wk, bk, Wv, bv);

    // 2) RoPE on Q and K
    rope_kernel<<<(1 << 22) / 256, 256>>>();

    // 3) Flash attention
    cudaFuncSetAttribute(flash_kernel,
                         cudaFuncAttributeMaxDynamicSharedMemorySize, FA_SMEM);
    flash_kernel<<<dim3(SQ / 64, NB * NH), 256, FA_SMEM>>>();

    // 4) Output projection
    out_gemm<<<dim3(8, 32), 256>>>(Wo, bo, out);
}

// round 4
// speedup vs baseline: 1.5113x; 1.5113x over previous
#include <cuda_runtime.h>
#include <cuda_bf16.h>
#include <math.h>
#include <stdint.h>

#define SQ   2048
#define NB   2
#define NH   16
#define DKH  64
#define DM   1024
#define MROWS 4096   // NB*SQ

// ---------------------------------------------------------------------------
// Scratch (__device__ globals; allocation-free rule)
// ---------------------------------------------------------------------------
__device__ float g_scratch[4ull * MROWS * DM];           // Q,K,V,A fp32
#define g_Q (g_scratch)
#define g_K (g_scratch + 1ull * MROWS * DM)
#define g_V (g_scratch + 2ull * MROWS * DM)
#define g_A (g_scratch + 3ull * MROWS * DM)

// bf16 split scratch: x_hi, x_lo, wt[4]{hi,lo}, a_hi, a_lo
#define BF_XHI  0ull
#define BF_XLO  (1ull * MROWS * DM)
#define BF_WT   (2ull * MROWS * DM)                       // 8 x DM*DM
#define BF_AHI  (BF_WT + 8ull * DM * DM)
#define BF_ALO  (BF_AHI + 1ull * MROWS * DM)
__device__ __nv_bfloat16 g_bf[BF_ALO + 1ull * MROWS * DM];

// ---------------------------------------------------------------------------
// Helpers (sm_100-safe: cp.async, ldmatrix, mma.sync only)
// ---------------------------------------------------------------------------
__device__ __forceinline__ uint32_t smem_u32(const void* p) {
    uint32_t a;
    asm("{ .reg .u64 t; cvta.to.shared.u64 t, %1; cvt.u32.u64 %0, t; }"
        : "=r"(a) : "l"(p));
    return a;
}

// SW64 swizzle for 64B rows (8-row atom), conflict-free ldmatrix
__device__ __forceinline__ uint32_t sw64(uint32_t off) {
    return off ^ ((off >> 3) & 0x30);
}

__device__ __forceinline__ void ldm_x4(uint32_t* r, uint32_t addr) {
    asm volatile("ldmatrix.sync.aligned.m8n8.x4.shared.b16 {%0,%1,%2,%3}, [%4];"
                 : "=r"(r[0]), "=r"(r[1]), "=r"(r[2]), "=r"(r[3]) : "r"(addr));
}
__device__ __forceinline__ void ldm_x2(uint32_t* r, uint32_t addr) {
    asm volatile("ldmatrix.sync.aligned.m8n8.x2.shared.b16 {%0,%1}, [%2];"
                 : "=r"(r[0]), "=r"(r[1]) : "r"(addr));
}

__device__ __forceinline__ void mma_bf16(float* d, const uint32_t* a,
                                         const uint32_t* b) {
    asm volatile(
        "mma.sync.aligned.m16n8k16.row.col.f32.bf16.bf16.f32 "
        "{%0,%1,%2,%3}, {%4,%5,%6,%7}, {%8,%9}, {%0,%1,%2,%3};"
        : "+f"(d[0]), "+f"(d[1]), "+f"(d[2]), "+f"(d[3])
        : "r"(a[0]), "r"(a[1]), "r"(a[2]), "r"(a[3]), "r"(b[0]), "r"(b[1]));
}

__device__ __forceinline__ void cp_async16(uint32_t dst, const void* src) {
    asm volatile("cp.async.cg.shared.global [%0], [%1], 16;"
                 :: "r"(dst), "l"(src));
}
#define CP_COMMIT() asm volatile("cp.async.commit_group;" ::: "memory")
#define CP_WAIT(n)  asm volatile("cp.async.wait_group %0;" :: "n"(n) : "memory")

// ---------------------------------------------------------------------------
// Prep: fp32 -> (bf16 hi, bf16 lo) split, 4 elems/thread
// ---------------------------------------------------------------------------
__global__ __launch_bounds__(256) void split_kernel(
    const float* __restrict__ src, __nv_bfloat16* __restrict__ hi,
    __nv_bfloat16* __restrict__ lo)
{
    size_t i = (size_t)(blockIdx.x * 256 + threadIdx.x) * 4;
    float4 v = *(const float4*)(src + i);
    __nv_bfloat16 h0 = __float2bfloat16_rn(v.x);
    __nv_bfloat16 h1 = __float2bfloat16_rn(v.y);
    __nv_bfloat16 h2 = __float2bfloat16_rn(v.z);
    __nv_bfloat16 h3 = __float2bfloat16_rn(v.w);
    __nv_bfloat16 l0 = __float2bfloat16_rn(v.x - __bfloat162float(h0));
    __nv_bfloat16 l1 = __float2bfloat16_rn(v.y - __bfloat162float(h1));
    __nv_bfloat16 l2 = __float2bfloat16_rn(v.z - __bfloat162float(h2));
    __nv_bfloat16 l3 = __float2bfloat16_rn(v.w - __bfloat162float(h3));
    ((__nv_bfloat162*)(hi + i))[0] = __nv_bfloat162(h0, h1);
    ((__nv_bfloat162*)(hi + i))[1] = __nv_bfloat162(h2, h3);
    ((__nv_bfloat162*)(lo + i))[0] = __nv_bfloat162(l0, l1);
    ((__nv_bfloat162*)(lo + i))[1] = __nv_bfloat162(l2, l3);
}

// ---------------------------------------------------------------------------
// Prep: transpose + split the 4 weight matrices W[k][n] -> Wt_hi/lo[n][k]
// ---------------------------------------------------------------------------
__global__ __launch_bounds__(256) void wsplit_kernel(
    const float* __restrict__ W0, const float* __restrict__ W1,
    const float* __restrict__ W2, const float* __restrict__ W3)
{
    __shared__ float t[32][33];
    const float* W = (blockIdx.z == 0) ? W0 : (blockIdx.z == 1) ? W1
                   : (blockIdx.z == 2) ? W2 : W3;
    __nv_bfloat16* whi = g_bf + BF_WT + (size_t)(2 * blockIdx.z) * DM * DM;
    __nv_bfloat16* wlo = whi + (size_t)DM * DM;
    int tx = threadIdx.x, ty = threadIdx.y;
    int n = blockIdx.x * 32 + tx;
#pragma unroll
    for (int i = 0; i < 32; i += 8)
        t[ty + i][tx] = W[(size_t)(blockIdx.y * 32 + ty + i) * DM + n];
    __syncthreads();
#pragma unroll
    for (int i = 0; i < 32; i += 8) {
        float v = t[tx][ty + i];
        __nv_bfloat16 h = __float2bfloat16_rn(v);
        __nv_bfloat16 l = __float2bfloat16_rn(v - __bfloat162float(h));
        size_t o = (size_t)(blockIdx.x * 32 + ty + i) * DM + blockIdx.y * 32 + tx;
        whi[o] = h;
        wlo[o] = l;
    }
}

// ---------------------------------------------------------------------------
// mma.sync bf16-split GEMM: C[4096,1024] = A @ W^T(+bias).
// A as (Ahi,Alo)[m][k]; B as (Bhi,Blo)[n][k] (K-major). Grid (8,32), 256 thr.
// CTA tile 128x128; warp grid 2(M)x4(N); warp tile 64x32 (4 m16 x 4 n8).
// K chunks of 32 bf16 (64B SW64 rows); double-buffered cp.async pipeline.
// ---------------------------------------------------------------------------
#define KCH 32
#define STG_T 8192                 // 128 rows * 64B per tile
#define STG_B (4 * STG_T)          // Ah, Al, Bh, Bl
#define MM_SMEM (2 * STG_B + 1024)

__global__ __launch_bounds__(256) void mm_gemm(
    const __nv_bfloat16* __restrict__ Ahi, const __nv_bfloat16* __restrict__ Alo,
    const __nv_bfloat16* __restrict__ Bhi, const __nv_bfloat16* __restrict__ Blo,
    const float* __restrict__ bias, float* __restrict__ C)
{
    extern __shared__ char smraw[];
    const uint32_t sbase = (smem_u32(smraw) + 1023) & ~1023u;

    const int tid  = threadIdx.x;
    const int wid  = tid >> 5, lane = tid & 31;
    const int m0   = blockIdx.y * 128, n0 = blockIdx.x * 128;
    const int wm   = (wid >> 2) * 64, wn = (wid & 3) * 32;

    float acc[4][4][4];
#pragma unroll
    for (int i = 0; i < 4; i++)
#pragma unroll
        for (int j = 0; j < 4; j++)
#pragma unroll
            for (int r = 0; r < 4; r++) acc[i][j][r] = 0.f;

    // ---- stage loader: 2048 16B chunks (4 tiles x 128 rows x 4 chunks) ----
    auto load_stage = [&](int kt, int buf) {
        const uint32_t bb = sbase + buf * STG_B;
#pragma unroll
        for (int it = 0; it < 8; it++) {
            int i = it * 256 + tid;
            int tile = i >> 9, idx = i & 511;
            int r = idx >> 2, c = idx & 3;
            uint32_t dst = bb + tile * STG_T + sw64((uint32_t)(r * 64 + c * 16));
            size_t off = (tile < 2)
                ? (size_t)(m0 + r) * DM + kt * KCH + c * 8
                : (size_t)(n0 + r) * DM + kt * KCH + c * 8;
            const __nv_bfloat16* src =
                (tile == 0) ? Ahi + off : (tile == 1) ? Alo + off
              : (tile == 2) ? Bhi + off : Blo + off;
            cp_async16(dst, src);
        }
    };

    load_stage(0, 0);
    CP_COMMIT();

    for (int kt = 0; kt < DM / KCH; kt++) {
        const int buf = kt & 1;
        if (kt < DM / KCH - 1) {
            load_stage(kt + 1, buf ^ 1);
            CP_COMMIT();
            CP_WAIT(1);
        } else {
            CP_WAIT(0);
        }
        __syncthreads();

        const uint32_t bb = sbase + buf * STG_B;
#pragma unroll
        for (int ks = 0; ks < 2; ks++) {        // two k16 steps per chunk
            uint32_t ah[4][4], al[4][4];
#pragma unroll
            for (int mt = 0; mt < 4; mt++) {
                int row = wm + mt * 16 + (lane & 15);
                int c = ks * 2 + (lane >> 4);
                uint32_t so = sw64((uint32_t)(row * 64 + c * 16));
                ldm_x4(ah[mt], bb + 0 * STG_T + so);
                ldm_x4(al[mt], bb + 1 * STG_T + so);
            }
            uint32_t bh[4][2], bl[4][2];
#pragma unroll
            for (int nt = 0; nt < 4; nt++) {
                int row = wn + nt * 8 + (lane & 7);
                int c = ks * 2 + ((lane >> 3) & 1);
                uint32_t so = sw64((uint32_t)(row * 64 + c * 16));
                ldm_x2(bh[nt], bb + 2 * STG_T + so);
                ldm_x2(bl[nt], bb + 3 * STG_T + so);
            }
#pragma unroll
            for (int mt = 0; mt < 4; mt++)
#pragma unroll
                for (int nt = 0; nt < 4; nt++) {
                    mma_bf16(acc[mt][nt], ah[mt], bh[nt]);
                    mma_bf16(acc[mt][nt], ah[mt], bl[nt]);
                    mma_bf16(acc[mt][nt], al[mt], bh[nt]);
                }
        }
        __syncthreads();
    }

    // ---- epilogue: bias + row-major store ----
    const int g = lane >> 2, t = lane & 3;
#pragma unroll
    for (int mt = 0; mt < 4; mt++) {
        int r0 = m0 + wm + mt * 16 + g;
#pragma unroll
        for (int nt = 0; nt < 4; nt++) {
            int col = n0 + wn + nt * 8 + t * 2;
            float2 bv = *(const float2*)&bias[col];
            float2 o0, o1;
            o0.x = acc[mt][nt][0] + bv.x;
            o0.y = acc[mt][nt][1] + bv.y;
            o1.x = acc[mt][nt][2] + bv.x;
            o1.y = acc[mt][nt][3] + bv.y;
            *(float2*)&C[(size_t)r0 * DM + col] = o0;
            *(float2*)&C[(size_t)(r0 + 8) * DM + col] = o1;
        }
    }
}

// ---------------------------------------------------------------------------
// RoPE on g_Q and g_K in place ([b*S+s][1024] layout, head h at col h*64).
// ---------------------------------------------------------------------------
__global__ __launch_bounds__(256) void rope_kernel()
{
    int tid = blockIdx.x * blockDim.x + threadIdx.x;   // 0 .. 2^22-1
    int j  = tid & 31;
    int s  = (tid >> 5) & (SQ - 1);
    int bh = (tid >> 16) & 31;
    int b = bh >> 4, h = bh & 15;
    float* base = (((tid >> 21) & 1) ? g_K : g_Q)
                + ((size_t)(b * SQ + s)) * DM + h * DKH;

    float invf = (float)pow(10000.0, -(double)j / 32.0);
    float ang = (float)s * invf;
    float sn, c;
    sincosf(ang, &sn, &c);
    float x1 = base[j], x2 = base[j + 32];
    base[j]      = x1 * c - x2 * sn;
    base[j + 32] = x1 * sn + x2 * c;
}

// ---------------------------------------------------------------------------
// Flash attention, fp32 SIMT (reads [b*S+s][1024] layout).
// ---------------------------------------------------------------------------
#define FA_STRIDE 68
#define FA_SMEM (4 * 64 * FA_STRIDE * 4)

__global__ __launch_bounds__(256) void flash_kernel()
{
    extern __shared__ float sm[];
    float* Qt = sm;                       // [64][68] (d-major)
    float* Kt = sm + 64 * FA_STRIDE;      // [64][68] (d-major)
    float* Vs = sm + 2 * 64 * FA_STRIDE;  // [64][68] (k-major)
    float* Pt = sm + 3 * 64 * FA_STRIDE;  // [64][68] (k-major)

    const int bh = blockIdx.y;
    const int qb = blockIdx.x;
    const int tid = threadIdx.x;
    const int ty = tid >> 4, tx = tid & 15;
    const int b = bh >> 4, h = bh & 15;

    const float* Qg = g_Q + ((size_t)(b * SQ + qb * 64)) * DM + h * DKH;
    const float* Kg = g_K + ((size_t)(b * SQ)) * DM + h * DKH;
    const float* Vg = g_V + ((size_t)(b * SQ)) * DM + h * DKH;

    for (int it = tid; it < 1024; it += 256) {
        int q = it >> 4, dv = (it & 15) << 2;
        float4 v = *(const float4*)(Qg + (size_t)q * DM + dv);
        Qt[(dv + 0) * FA_STRIDE + q] = v.x * 0.125f;
        Qt[(dv + 1) * FA_STRIDE + q] = v.y * 0.125f;
        Qt[(dv + 2) * FA_STRIDE + q] = v.z * 0.125f;
        Qt[(dv + 3) * FA_STRIDE + q] = v.w * 0.125f;
    }

    float m_i[4], l_i[4], o[4][4];
#pragma unroll
    for (int i = 0; i < 4; i++) {
        m_i[i] = -1e30f; l_i[i] = 0.f;
#pragma unroll
        for (int j = 0; j < 4; j++) o[i][j] = 0.f;
    }

    for (int kt = 0; kt < SQ / 64; kt++) {
        const float* Kp = Kg + (size_t)(kt * 64) * DM;
        const float* Vp = Vg + (size_t)(kt * 64) * DM;
        for (int it = tid; it < 1024; it += 256) {
            int r = it >> 4, dv = (it & 15) << 2;
            float4 kv = *(const float4*)(Kp + (size_t)r * DM + dv);
            Kt[(dv + 0) * FA_STRIDE + r] = kv.x;
            Kt[(dv + 1) * FA_STRIDE + r] = kv.y;
            Kt[(dv + 2) * FA_STRIDE + r] = kv.z;
            Kt[(dv + 3) * FA_STRIDE + r] = kv.w;
            *(float4*)&Vs[r * FA_STRIDE + dv] = *(const float4*)(Vp + (size_t)r * DM + dv);
        }
        __syncthreads();

        float sacc[4][4] = {};
#pragma unroll 4
        for (int d = 0; d < 64; d++) {
            float4 qv = *(const float4*)&Qt[d * FA_STRIDE + ty * 4];
            float4 kv = *(const float4*)&Kt[d * FA_STRIDE + tx * 4];
            float qa[4] = {qv.x, qv.y, qv.z, qv.w};
            float ka[4] = {kv.x, kv.y, kv.z, kv.w};
#pragma unroll
            for (int i = 0; i < 4; i++)
#pragma unroll
                for (int j = 0; j < 4; j++)
                    sacc[i][j] = fmaf(qa[i], ka[j], sacc[i][j]);
        }

#pragma unroll
        for (int i = 0; i < 4; i++) {
            float mx = fmaxf(fmaxf(sacc[i][0], sacc[i][1]),
                             fmaxf(sacc[i][2], sacc[i][3]));
#pragma unroll
            for (int off = 8; off >= 1; off >>= 1)
                mx = fmaxf(mx, __shfl_xor_sync(0xffffffffu, mx, off));
            float mnew = fmaxf(m_i[i], mx);
            float alpha = __expf(m_i[i] - mnew);
            float rs = 0.f;
#pragma unroll
            for (int jj = 0; jj < 4; jj++) {
                float p = __expf(sacc[i][jj] - mnew);
                Pt[(tx * 4 + jj) * FA_STRIDE + ty * 4 + i] = p;
                rs += p;
            }
#pragma unroll
            for (int off = 8; off >= 1; off >>= 1)
                rs += __shfl_xor_sync(0xffffffffu, rs, off);
            l_i[i] = l_i[i] * alpha + rs;
            m_i[i] = mnew;
#pragma unroll
            for (int jj = 0; jj < 4; jj++) o[i][jj] *= alpha;
        }
        __syncthreads();

#pragma unroll 4
        for (int k = 0; k < 64; k++) {
            float4 pv = *(const float4*)&Pt[k * FA_STRIDE + ty * 4];
            float4 vv = *(const float4*)&Vs[k * FA_STRIDE + tx * 4];
            float pa[4] = {pv.x, pv.y, pv.z, pv.w};
            float va[4] = {vv.x, vv.y, vv.z, vv.w};
#pragma unroll
            for (int i = 0; i < 4; i++)
#pragma unroll
                for (int j = 0; j < 4; j++)
                    o[i][j] = fmaf(pa[i], va[j], o[i][j]);
        }
        __syncthreads();
    }

#pragma unroll
    for (int i = 0; i < 4; i++) {
        float inv_l = 1.f / l_i[i];
        int s = qb * 64 + ty * 4 + i;
#pragma unroll
        for (int j = 0; j < 4; j++) {
            g_A[((size_t)(b * SQ + s)) * DM + h * DKH + tx * 4 + j] = o[i][j] * inv_l;
        }
    }
}

// ---------------------------------------------------------------------------
extern "C" void kernel_launch(void* const* d_in, const int* in_sizes, int n_in,
                              void* d_out, int out_size)
{
    const float* x  = (const float*)d_in[0];
    const float* Wq = (const float*)d_in[1];
    const float* bq = (const float*)d_in[2];
    const float* Wk = (const float*)d_in[3];
    const float* bk = (const float*)d_in[4];
    const float* Wv = (const float*)d_in[5];
    const float* bv = (const float*)d_in[6];
    const float* Wo = (const float*)d_in[7];
    const float* bo = (const float*)d_in[8];
    float* out = (float*)d_out;

    __nv_bfloat16* bf = nullptr;
    cudaGetSymbolAddress((void**)&bf, g_bf);
    float* fs = nullptr;
    cudaGetSymbolAddress((void**)&fs, g_scratch);
    float* gQ = fs;
    float* gK = fs + 1ull * MROWS * DM;
    float* gV = fs + 2ull * MROWS * DM;
    float* gA = fs + 3ull * MROWS * DM;

    cudaFuncSetAttribute(mm_gemm,
                         cudaFuncAttributeMaxDynamicSharedMemorySize, MM_SMEM);
    cudaFuncSetAttribute(flash_kernel,
                         cudaFuncAttributeMaxDynamicSharedMemorySize, FA_SMEM);

    // 1) split x -> bf16 hi/lo; transpose+split the 4 weights
    split_kernel<<<MROWS * DM / 1024, 256>>>(x, bf + BF_XHI, bf + BF_XLO);
    wsplit_kernel<<<dim3(32, 32, 4), dim3(32, 8)>>>(Wq, Wk, Wv, Wo);

    // 2) Q/K/V projections on tensor cores (mma.sync bf16-split)
    mm_gemm<<<dim3(8, 32), 256, MM_SMEM>>>(
        bf + BF_XHI, bf + BF_XLO,
        bf + BF_WT + 0ull * DM * DM, bf + BF_WT + 1ull * DM * DM, bq, gQ);
    mm_gemm<<<dim3(8, 32), 256, MM_SMEM>>>(
        bf + BF_XHI, bf + BF_XLO,
        bf + BF_WT + 2ull * DM * DM, bf + BF_WT + 3ull * DM * DM, bk, gK);
    mm_gemm<<<dim3(8, 32), 256, MM_SMEM>>>(
        bf + BF_XHI, bf + BF_XLO,
        bf + BF_WT + 4ull * DM * DM, bf + BF_WT + 5ull * DM * DM, bv, gV);

    // 3) RoPE
    rope_kernel<<<(1 << 22) / 256, 256>>>();

    // 4) Flash attention (fp32 SIMT)
    flash_kernel<<<dim3(SQ / 64, NB * NH), 256, FA_SMEM>>>();

    // 5) split attn output, output projection on tensor cores
    split_kernel<<<MROWS * DM / 1024, 256>>>(gA, bf + BF_AHI, bf + BF_ALO);
    mm_gemm<<<dim3(8, 32), 256, MM_SMEM>>>(
        bf + BF_AHI, bf + BF_ALO,
        bf + BF_WT + 6ull * DM * DM, bf + BF_WT + 7ull * DM * DM, bo, out);
}

// round 5
// speedup vs baseline: 2.5424x; 1.6823x over previous
#include <cuda_runtime.h>
#include <cuda_bf16.h>
#include <math.h>
#include <stdint.h>

#define SQ   2048
#define NB   2
#define NH   16
#define DKH  64
#define DM   1024
#define MROWS 4096   // NB*SQ

// ---------------------------------------------------------------------------
// Scratch (__device__ globals; allocation-free rule)
// ---------------------------------------------------------------------------
__device__ float g_scratch[4ull * MROWS * DM];           // Q,K,V,A fp32
#define g_Q (g_scratch)
#define g_K (g_scratch + 1ull * MROWS * DM)
#define g_V (g_scratch + 2ull * MROWS * DM)
#define g_A (g_scratch + 3ull * MROWS * DM)

// bf16 split scratch: x_hi, x_lo, wt[4]{hi,lo}, a_hi, a_lo
#define BF_XHI  0ull
#define BF_XLO  (1ull * MROWS * DM)
#define BF_WT   (2ull * MROWS * DM)                       // 8 x DM*DM
#define BF_AHI  (BF_WT + 8ull * DM * DM)
#define BF_ALO  (BF_AHI + 1ull * MROWS * DM)
__device__ __nv_bfloat16 g_bf[BF_ALO + 1ull * MROWS * DM];

// ---------------------------------------------------------------------------
// Helpers (sm_100-safe: cp.async, ldmatrix, mma.sync only)
// ---------------------------------------------------------------------------
__device__ __forceinline__ uint32_t smem_u32(const void* p) {
    uint32_t a;
    asm("{ .reg .u64 t; cvta.to.shared.u64 t, %1; cvt.u32.u64 %0, t; }"
        : "=r"(a) : "l"(p));
    return a;
}

__device__ __forceinline__ uint32_t sw64(uint32_t off) {
    return off ^ ((off >> 3) & 0x30);
}
__device__ __forceinline__ uint32_t sw128(uint32_t off) {
    return off ^ ((off >> 3) & 0x70);
}

__device__ __forceinline__ void ldm_x4(uint32_t* r, uint32_t addr) {
    asm volatile("ldmatrix.sync.aligned.m8n8.x4.shared.b16 {%0,%1,%2,%3}, [%4];"
                 : "=r"(r[0]), "=r"(r[1]), "=r"(r[2]), "=r"(r[3]) : "r"(addr));
}
__device__ __forceinline__ void ldm_x2(uint32_t* r, uint32_t addr) {
    asm volatile("ldmatrix.sync.aligned.m8n8.x2.shared.b16 {%0,%1}, [%2];"
                 : "=r"(r[0]), "=r"(r[1]) : "r"(addr));
}

__device__ __forceinline__ void mma_bf16(float* d, const uint32_t* a,
                                         const uint32_t* b) {
    asm volatile(
        "mma.sync.aligned.m16n8k16.row.col.f32.bf16.bf16.f32 "
        "{%0,%1,%2,%3}, {%4,%5,%6,%7}, {%8,%9}, {%0,%1,%2,%3};"
        : "+f"(d[0]), "+f"(d[1]), "+f"(d[2]), "+f"(d[3])
        : "r"(a[0]), "r"(a[1]), "r"(a[2]), "r"(a[3]), "r"(b[0]), "r"(b[1]));
}

__device__ __forceinline__ void cp_async16(uint32_t dst, const void* src) {
    asm volatile("cp.async.cg.shared.global [%0], [%1], 16;"
                 :: "r"(dst), "l"(src));
}
#define CP_COMMIT() asm volatile("cp.async.commit_group;" ::: "memory")
#define CP_WAIT(n)  asm volatile("cp.async.wait_group %0;" :: "n"(n) : "memory")

__device__ __forceinline__ uint32_t packbf2(float a, float b) {
    __nv_bfloat162 t = __floats2bfloat162_rn(a, b);
    return *(uint32_t*)&t;
}

// ---------------------------------------------------------------------------
// Prep: fp32 -> (bf16 hi, bf16 lo) split, 4 elems/thread
// ---------------------------------------------------------------------------
__global__ __launch_bounds__(256) void split_kernel(
    const float* __restrict__ src, __nv_bfloat16* __restrict__ hi,
    __nv_bfloat16* __restrict__ lo)
{
    size_t i = (size_t)(blockIdx.x * 256 + threadIdx.x) * 4;
    float4 v = *(const float4*)(src + i);
    __nv_bfloat16 h0 = __float2bfloat16_rn(v.x);
    __nv_bfloat16 h1 = __float2bfloat16_rn(v.y);
    __nv_bfloat16 h2 = __float2bfloat16_rn(v.z);
    __nv_bfloat16 h3 = __float2bfloat16_rn(v.w);
    __nv_bfloat16 l0 = __float2bfloat16_rn(v.x - __bfloat162float(h0));
    __nv_bfloat16 l1 = __float2bfloat16_rn(v.y - __bfloat162float(h1));
    __nv_bfloat16 l2 = __float2bfloat16_rn(v.z - __bfloat162float(h2));
    __nv_bfloat16 l3 = __float2bfloat16_rn(v.w - __bfloat162float(h3));
    ((__nv_bfloat162*)(hi + i))[0] = __nv_bfloat162(h0, h1);
    ((__nv_bfloat162*)(hi + i))[1] = __nv_bfloat162(h2, h3);
    ((__nv_bfloat162*)(lo + i))[0] = __nv_bfloat162(l0, l1);
    ((__nv_bfloat162*)(lo + i))[1] = __nv_bfloat162(l2, l3);
}

// ---------------------------------------------------------------------------
// Prep: transpose + split the 4 weight matrices W[k][n] -> Wt_hi/lo[n][k]
// ---------------------------------------------------------------------------
__global__ __launch_bounds__(256) void wsplit_kernel(
    const float* __restrict__ W0, const float* __restrict__ W1,
    const float* __restrict__ W2, const float* __restrict__ W3)
{
    __shared__ float t[32][33];
    const float* W = (blockIdx.z == 0) ? W0 : (blockIdx.z == 1) ? W1
                   : (blockIdx.z == 2) ? W2 : W3;
    __nv_bfloat16* whi = g_bf + BF_WT + (size_t)(2 * blockIdx.z) * DM * DM;
    __nv_bfloat16* wlo = whi + (size_t)DM * DM;
    int tx = threadIdx.x, ty = threadIdx.y;
    int n = blockIdx.x * 32 + tx;
#pragma unroll
    for (int i = 0; i < 32; i += 8)
        t[ty + i][tx] = W[(size_t)(blockIdx.y * 32 + ty + i) * DM + n];
    __syncthreads();
#pragma unroll
    for (int i = 0; i < 32; i += 8) {
        float v = t[tx][ty + i];
        __nv_bfloat16 h = __float2bfloat16_rn(v);
        __nv_bfloat16 l = __float2bfloat16_rn(v - __bfloat162float(h));
        size_t o = (size_t)(blockIdx.x * 32 + ty + i) * DM + blockIdx.y * 32 + tx;
        whi[o] = h;
        wlo[o] = l;
    }
}

// ---------------------------------------------------------------------------
// mma.sync bf16-split GEMM (unchanged from R4; proven)
// ---------------------------------------------------------------------------
#define KCH 32
#define STG_T 8192
#define STG_B (4 * STG_T)
#define MM_SMEM (2 * STG_B + 1024)

__global__ __launch_bounds__(256) void mm_gemm(
    const __nv_bfloat16* __restrict__ Ahi, const __nv_bfloat16* __restrict__ Alo,
    const __nv_bfloat16* __restrict__ Bhi, const __nv_bfloat16* __restrict__ Blo,
    const float* __restrict__ bias, float* __restrict__ C)
{
    extern __shared__ char smraw[];
    const uint32_t sbase = (smem_u32(smraw) + 1023) & ~1023u;

    const int tid  = threadIdx.x;
    const int wid  = tid >> 5, lane = tid & 31;
    const int m0   = blockIdx.y * 128, n0 = blockIdx.x * 128;
    const int wm   = (wid >> 2) * 64, wn = (wid & 3) * 32;

    float acc[4][4][4];
#pragma unroll
    for (int i = 0; i < 4; i++)
#pragma unroll
        for (int j = 0; j < 4; j++)
#pragma unroll
            for (int r = 0; r < 4; r++) acc[i][j][r] = 0.f;

    auto load_stage = [&](int kt, int buf) {
        const uint32_t bb = sbase + buf * STG_B;
#pragma unroll
        for (int it = 0; it < 8; it++) {
            int i = it * 256 + tid;
            int tile = i >> 9, idx = i & 511;
            int r = idx >> 2, c = idx & 3;
            uint32_t dst = bb + tile * STG_T + sw64((uint32_t)(r * 64 + c * 16));
            size_t off = (tile < 2)
                ? (size_t)(m0 + r) * DM + kt * KCH + c * 8
                : (size_t)(n0 + r) * DM + kt * KCH + c * 8;
            const __nv_bfloat16* src =
                (tile == 0) ? Ahi + off : (tile == 1) ? Alo + off
              : (tile == 2) ? Bhi + off : Blo + off;
            cp_async16(dst, src);
        }
    };

    load_stage(0, 0);
    CP_COMMIT();

    for (int kt = 0; kt < DM / KCH; kt++) {
        const int buf = kt & 1;
        if (kt < DM / KCH - 1) {
            load_stage(kt + 1, buf ^ 1);
            CP_COMMIT();
            CP_WAIT(1);
        } else {
            CP_WAIT(0);
        }
        __syncthreads();

        const uint32_t bb = sbase + buf * STG_B;
#pragma unroll
        for (int ks = 0; ks < 2; ks++) {
            uint32_t ah[4][4], al[4][4];
#pragma unroll
            for (int mt = 0; mt < 4; mt++) {
                int row = wm + mt * 16 + (lane & 15);
                int c = ks * 2 + (lane >> 4);
                uint32_t so = sw64((uint32_t)(row * 64 + c * 16));
                ldm_x4(ah[mt], bb + 0 * STG_T + so);
                ldm_x4(al[mt], bb + 1 * STG_T + so);
            }
            uint32_t bh[4][2], bl[4][2];
#pragma unroll
            for (int nt = 0; nt < 4; nt++) {
                int row = wn + nt * 8 + (lane & 7);
                int c = ks * 2 + ((lane >> 3) & 1);
                uint32_t so = sw64((uint32_t)(row * 64 + c * 16));
                ldm_x2(bh[nt], bb + 2 * STG_T + so);
                ldm_x2(bl[nt], bb + 3 * STG_T + so);
            }
#pragma unroll
            for (int mt = 0; mt < 4; mt++)
#pragma unroll
                for (int nt = 0; nt < 4; nt++) {
                    mma_bf16(acc[mt][nt], ah[mt], bh[nt]);
                    mma_bf16(acc[mt][nt], ah[mt], bl[nt]);
                    mma_bf16(acc[mt][nt], al[mt], bh[nt]);
                }
        }
        __syncthreads();
    }

    const int g = lane >> 2, t = lane & 3;
#pragma unroll
    for (int mt = 0; mt < 4; mt++) {
        int r0 = m0 + wm + mt * 16 + g;
#pragma unroll
        for (int nt = 0; nt < 4; nt++) {
            int col = n0 + wn + nt * 8 + t * 2;
            float2 bv = *(const float2*)&bias[col];
            float2 o0, o1;
            o0.x = acc[mt][nt][0] + bv.x;
            o0.y = acc[mt][nt][1] + bv.y;
            o1.x = acc[mt][nt][2] + bv.x;
            o1.y = acc[mt][nt][3] + bv.y;
            *(float2*)&C[(size_t)r0 * DM + col] = o0;
            *(float2*)&C[(size_t)(r0 + 8) * DM + col] = o1;
        }
    }
}

// ---------------------------------------------------------------------------
// RoPE on g_Q and g_K in place ([b*S+s][1024] layout, head h at col h*64).
// ---------------------------------------------------------------------------
__global__ __launch_bounds__(256) void rope_kernel()
{
    int tid = blockIdx.x * blockDim.x + threadIdx.x;   // 0 .. 2^22-1
    int j  = tid & 31;
    int s  = (tid >> 5) & (SQ - 1);
    int bh = (tid >> 16) & 31;
    int b = bh >> 4, h = bh & 15;
    float* base = (((tid >> 21) & 1) ? g_K : g_Q)
                + ((size_t)(b * SQ + s)) * DM + h * DKH;

    float invf = (float)pow(10000.0, -(double)j / 32.0);
    float ang = (float)s * invf;
    float sn, c;
    sincosf(ang, &sn, &c);
    float x1 = base[j], x2 = base[j + 32];
    base[j]      = x1 * c - x2 * sn;
    base[j + 32] = x1 * sn + x2 * c;
}

// ---------------------------------------------------------------------------
// Tensor-core flash attention (mma.sync bf16-split, online softmax in regs).
// Grid (SQ/128, NB*NH), 256 threads = 8 warps; warp = one m16 q-band.
// Per key-tile of 64: K->(hi,lo) K-major smem; V->(hi,lo) TRANSPOSED Vt[d][k].
// S = Q Kt^T (3-MMA split), softmax in regs, O += P Vt (3-MMA split).
// Q frags loaded once (32 regs) and reused across all 32 key tiles.
// ---------------------------------------------------------------------------
#define FQH 0
#define FQL 16384
#define FKH 32768
#define FKL 40960
#define FVH 49152
#define FVL 57344
#define FA2_SMEM (65536 + 1024)

__global__ __launch_bounds__(256) void flash_tc()
{
    extern __shared__ char smraw[];
    const uint32_t sb = (smem_u32(smraw) + 1023) & ~1023u;

    const int tid = threadIdx.x;
    const int wid = tid >> 5, lane = tid & 31;
    const int b = blockIdx.y >> 4, h = blockIdx.y & 15;
    const int q0 = blockIdx.x * 128;

    const float* Qg = g_Q + ((size_t)(b * SQ + q0)) * DM + h * DKH;
    const float* Kg = g_K + ((size_t)(b * SQ)) * DM + h * DKH;
    const float* Vg = g_V + ((size_t)(b * SQ)) * DM + h * DKH;

    // ---- load Q tile (128x64), scale 0.125, split -> QH/QL smem ----
#pragma unroll
    for (int it = 0; it < 8; it++) {
        int c = it * 256 + tid;          // 0..2047 float4 chunks
        int row = c >> 4, d4 = (c & 15) << 2;
        float4 v = *(const float4*)(Qg + (size_t)row * DM + d4);
        v.x *= 0.125f; v.y *= 0.125f; v.z *= 0.125f; v.w *= 0.125f;
        float hx = __bfloat162float(__float2bfloat16_rn(v.x));
        float hy = __bfloat162float(__float2bfloat16_rn(v.y));
        float hz = __bfloat162float(__float2bfloat16_rn(v.z));
        float hw = __bfloat162float(__float2bfloat16_rn(v.w));
        uint2 hp, lp;
        hp.x = packbf2(hx, hy); hp.y = packbf2(hz, hw);
        lp.x = packbf2(v.x - hx, v.y - hy); lp.y = packbf2(v.z - hz, v.w - hw);
        uint32_t so = sw128((uint32_t)(row * 128 + d4 * 2));
        *(uint2*)(smraw + (sb - smem_u32(smraw)) + FQH + so) = hp;
        *(uint2*)(smraw + (sb - smem_u32(smraw)) + FQL + so) = lp;
    }
    __syncthreads();

    // ---- Q fragments (held in regs for whole kernel) ----
    uint32_t qh[4][4], ql[4][4];
#pragma unroll
    for (int kt = 0; kt < 4; kt++) {
        int row = wid * 16 + (lane & 15);
        uint32_t so = sw128((uint32_t)(row * 128 + kt * 32 + (lane >> 4) * 16));
        ldm_x4(qh[kt], sb + FQH + so);
        ldm_x4(ql[kt], sb + FQL + so);
    }

    float m_i[2] = {-1e30f, -1e30f};
    float l_i[2] = {0.f, 0.f};
    float o[8][4];
#pragma unroll
    for (int nt = 0; nt < 8; nt++)
#pragma unroll
        for (int r = 0; r < 4; r++) o[nt][r] = 0.f;

    for (int ktile = 0; ktile < SQ / 64; ktile++) {
        __syncthreads();   // previous iteration's smem reads done
        // ---- load K (K-major) and V (transposed) tiles, split hi/lo ----
        const float* Kp = Kg + (size_t)(ktile * 64) * DM;
        const float* Vp = Vg + (size_t)(ktile * 64) * DM;
#pragma unroll
        for (int it = 0; it < 4; it++) {
            int c = it * 256 + tid;      // 0..1023 float4 chunks
            int row = c >> 4, d4 = (c & 15) << 2;
            {
                float4 v = *(const float4*)(Kp + (size_t)row * DM + d4);
                float hx = __bfloat162float(__float2bfloat16_rn(v.x));
                float hy = __bfloat162float(__float2bfloat16_rn(v.y));
                float hz = __bfloat162float(__float2bfloat16_rn(v.z));
                float hw = __bfloat162float(__float2bfloat16_rn(v.w));
                uint2 hp, lp;
                hp.x = packbf2(hx, hy); hp.y = packbf2(hz, hw);
                lp.x = packbf2(v.x - hx, v.y - hy);
                lp.y = packbf2(v.z - hz, v.w - hw);
                uint32_t so = sw128((uint32_t)(row * 128 + d4 * 2));
                *(uint2*)(smraw + (sb - smem_u32(smraw)) + FKH + so) = hp;
                *(uint2*)(smraw + (sb - smem_u32(smraw)) + FKL + so) = lp;
            }
            {
                float4 v = *(const float4*)(Vp + (size_t)row * DM + d4);
                float hv[4] = {
                    __bfloat162float(__float2bfloat16_rn(v.x)),
                    __bfloat162float(__float2bfloat16_rn(v.y)),
                    __bfloat162float(__float2bfloat16_rn(v.z)),
                    __bfloat162float(__float2bfloat16_rn(v.w))};
                float fv[4] = {v.x, v.y, v.z, v.w};
#pragma unroll
                for (int e = 0; e < 4; e++) {
                    uint32_t so = sw128((uint32_t)((d4 + e) * 128 + row * 2));
                    *(__nv_bfloat16*)(smraw + (sb - smem_u32(smraw)) + FVH + so)
                        = __float2bfloat16_rn(hv[e]);
                    *(__nv_bfloat16*)(smraw + (sb - smem_u32(smraw)) + FVL + so)
                        = __float2bfloat16_rn(fv[e] - hv[e]);
                }
            }
        }
        __syncthreads();

        // ---- S = Q K^T  (3-MMA split), warp m16 x 64 keys ----
        float sacc[8][4];
#pragma unroll
        for (int nt = 0; nt < 8; nt++)
#pragma unroll
            for (int r = 0; r < 4; r++) sacc[nt][r] = 0.f;

#pragma unroll
        for (int kt = 0; kt < 4; kt++) {
            uint32_t bh[8][2], bl[8][2];
#pragma unroll
            for (int nt = 0; nt < 8; nt++) {
                int row = nt * 8 + (lane & 7);
                uint32_t so = sw128((uint32_t)(row * 128 + kt * 32
                                               + ((lane >> 3) & 1) * 16));
                ldm_x2(bh[nt], sb + FKH + so);
                ldm_x2(bl[nt], sb + FKL + so);
            }
#pragma unroll
            for (int nt = 0; nt < 8; nt++) {
                mma_bf16(sacc[nt], qh[kt], bh[nt]);
                mma_bf16(sacc[nt], qh[kt], bl[nt]);
                mma_bf16(sacc[nt], ql[kt], bh[nt]);
            }
        }

        // ---- online softmax (rows lane>>2 and +8) ----
        float mx0 = -1e30f, mx1 = -1e30f;
#pragma unroll
        for (int nt = 0; nt < 8; nt++) {
            mx0 = fmaxf(mx0, fmaxf(sacc[nt][0], sacc[nt][1]));
            mx1 = fmaxf(mx1, fmaxf(sacc[nt][2], sacc[nt][3]));
        }
        mx0 = fmaxf(mx0, __shfl_xor_sync(0xffffffffu, mx0, 1));
        mx0 = fmaxf(mx0, __shfl_xor_sync(0xffffffffu, mx0, 2));
        mx1 = fmaxf(mx1, __shfl_xor_sync(0xffffffffu, mx1, 1));
        mx1 = fmaxf(mx1, __shfl_xor_sync(0xffffffffu, mx1, 2));
        float mn0 = fmaxf(m_i[0], mx0), mn1 = fmaxf(m_i[1], mx1);
        float al0 = __expf(m_i[0] - mn0), al1 = __expf(m_i[1] - mn1);
        float rs0 = 0.f, rs1 = 0.f;
#pragma unroll
        for (int nt = 0; nt < 8; nt++) {
            sacc[nt][0] = __expf(sacc[nt][0] - mn0);
            sacc[nt][1] = __expf(sacc[nt][1] - mn0);
            sacc[nt][2] = __expf(sacc[nt][2] - mn1);
            sacc[nt][3] = __expf(sacc[nt][3] - mn1);
            rs0 += sacc[nt][0] + sacc[nt][1];
            rs1 += sacc[nt][2] + sacc[nt][3];
        }
        rs0 += __shfl_xor_sync(0xffffffffu, rs0, 1);
        rs0 += __shfl_xor_sync(0xffffffffu, rs0, 2);
        rs1 += __shfl_xor_sync(0xffffffffu, rs1, 1);
        rs1 += __shfl_xor_sync(0xffffffffu, rs1, 2);
        l_i[0] = l_i[0] * al0 + rs0;
        l_i[1] = l_i[1] * al1 + rs1;
        m_i[0] = mn0; m_i[1] = mn1;
#pragma unroll
        for (int nt = 0; nt < 8; nt++) {
            o[nt][0] *= al0; o[nt][1] *= al0;
            o[nt][2] *= al1; o[nt][3] *= al1;
        }

        // ---- P -> bf16 hi/lo A-frags; O += P Vt (3-MMA split) ----
#pragma unroll
        for (int t = 0; t < 4; t++) {
            float p00 = sacc[2 * t][0], p01 = sacc[2 * t][1];
            float p02 = sacc[2 * t][2], p03 = sacc[2 * t][3];
            float p10 = sacc[2 * t + 1][0], p11 = sacc[2 * t + 1][1];
            float p12 = sacc[2 * t + 1][2], p13 = sacc[2 * t + 1][3];
            float h00 = __bfloat162float(__float2bfloat16_rn(p00));
            float h01 = __bfloat162float(__float2bfloat16_rn(p01));
            float h02 = __bfloat162float(__float2bfloat16_rn(p02));
            float h03 = __bfloat162float(__float2bfloat16_rn(p03));
            float h10 = __bfloat162float(__float2bfloat16_rn(p10));
            float h11 = __bfloat162float(__float2bfloat16_rn(p11));
            float h12 = __bfloat162float(__float2bfloat16_rn(p12));
            float h13 = __bfloat162float(__float2bfloat16_rn(p13));
            uint32_t ahf[4], alf[4];
            ahf[0] = packbf2(h00, h01); ahf[1] = packbf2(h02, h03);
            ahf[2] = packbf2(h10, h11); ahf[3] = packbf2(h12, h13);
            alf[0] = packbf2(p00 - h00, p01 - h01);
            alf[1] = packbf2(p02 - h02, p03 - h03);
            alf[2] = packbf2(p10 - h10, p11 - h11);
            alf[3] = packbf2(p12 - h12, p13 - h13);
#pragma unroll
            for (int nt = 0; nt < 8; nt++) {
                uint32_t vh[2], vl[2];
                int row = nt * 8 + (lane & 7);
                uint32_t so = sw128((uint32_t)(row * 128 + t * 32
                                               + ((lane >> 3) & 1) * 16));
                ldm_x2(vh, sb + FVH + so);
                ldm_x2(vl, sb + FVL + so);
                mma_bf16(o[nt], ahf, vh);
                mma_bf16(o[nt], ahf, vl);
                mma_bf16(o[nt], alf, vh);
            }
        }
    }

    // ---- epilogue: divide by l, store to g_A ----
    float inv0 = 1.f / l_i[0], inv1 = 1.f / l_i[1];
    int r0 = q0 + wid * 16 + (lane >> 2);
    float* Ap = g_A + ((size_t)(b * SQ)) * DM + h * DKH;
#pragma unroll
    for (int nt = 0; nt < 8; nt++) {
        int col = nt * 8 + (lane & 3) * 2;
        float2 v0, v1;
        v0.x = o[nt][0] * inv0; v0.y = o[nt][1] * inv0;
        v1.x = o[nt][2] * inv1; v1.y = o[nt][3] * inv1;
        *(float2*)(Ap + (size_t)r0 * DM + col) = v0;
        *(float2*)(Ap + (size_t)(r0 + 8) * DM + col) = v1;
    }
}

// ---------------------------------------------------------------------------
extern "C" void kernel_launch(void* const* d_in, const int* in_sizes, int n_in,
                              void* d_out, int out_size)
{
    const float* x  = (const float*)d_in[0];
    const float* Wq = (const float*)d_in[1];
    const float* bq = (const float*)d_in[2];
    const float* Wk = (const float*)d_in[3];
    const float* bk = (const float*)d_in[4];
    const float* Wv = (const float*)d_in[5];
    const float* bv = (const float*)d_in[6];
    const float* Wo = (const float*)d_in[7];
    const float* bo = (const float*)d_in[8];
    float* out = (float*)d_out;

    __nv_bfloat16* bf = nullptr;
    cudaGetSymbolAddress((void**)&bf, g_bf);
    float* fs = nullptr;
    cudaGetSymbolAddress((void**)&fs, g_scratch);
    float* gQ = fs;
    float* gK = fs + 1ull * MROWS * DM;
    float* gV = fs + 2ull * MROWS * DM;
    float* gA = fs + 3ull * MROWS * DM;

    cudaFuncSetAttribute(mm_gemm,
                         cudaFuncAttributeMaxDynamicSharedMemorySize, MM_SMEM);
    cudaFuncSetAttribute(flash_tc,
                         cudaFuncAttributeMaxDynamicSharedMemorySize, FA2_SMEM);

    // 1) split x -> bf16 hi/lo; transpose+split the 4 weights
    split_kernel<<<MROWS * DM / 1024, 256>>>(x, bf + BF_XHI, bf + BF_XLO);
    wsplit_kernel<<<dim3(32, 32, 4), dim3(32, 8)>>>(Wq, Wk, Wv, Wo);

    // 2) Q/K/V projections (mma.sync bf16-split)
    mm_gemm<<<dim3(8, 32), 256, MM_SMEM>>>(
        bf + BF_XHI, bf + BF_XLO,
        bf + BF_WT + 0ull * DM * DM, bf + BF_WT + 1ull * DM * DM, bq, gQ);
    mm_gemm<<<dim3(8, 32), 256, MM_SMEM>>>(
        bf + BF_XHI, bf + BF_XLO,
        bf + BF_WT + 2ull * DM * DM, bf + BF_WT + 3ull * DM * DM, bk, gK);
    mm_gemm<<<dim3(8, 32), 256, MM_SMEM>>>(
        bf + BF_XHI, bf + BF_XLO,
        bf + BF_WT + 4ull * DM * DM, bf + BF_WT + 5ull * DM * DM, bv, gV);

    // 3) RoPE
    rope_kernel<<<(1 << 22) / 256, 256>>>();

    // 4) Flash attention on tensor cores
    flash_tc<<<dim3(SQ / 128, NB * NH), 256, FA2_SMEM>>>();

    // 5) split attn output, output projection
    split_kernel<<<MROWS * DM / 1024, 256>>>(gA, bf + BF_AHI, bf + BF_ALO);
    mm_gemm<<<dim3(8, 32), 256, MM_SMEM>>>(
        bf + BF_AHI, bf + BF_ALO,
        bf + BF_WT + 6ull * DM * DM, bf + BF_WT + 7ull * DM * DM, bo, out);
}

// round 6
// speedup vs baseline: 3.1742x; 1.2485x over previous
#include <cuda_runtime.h>
#include <cuda_bf16.h>
#include <math.h>
#include <stdint.h>

#define SQ   2048
#define NB   2
#define NH   16
#define DKH  64
#define DM   1024
#define MROWS 4096   // NB*SQ

// ---------------------------------------------------------------------------
// Scratch (__device__ globals; allocation-free rule)
// ---------------------------------------------------------------------------
__device__ float g_scratch[4ull * MROWS * DM];           // Q,K,V,A fp32
#define g_Q (g_scratch)
#define g_K (g_scratch + 1ull * MROWS * DM)
#define g_V (g_scratch + 2ull * MROWS * DM)
#define g_A (g_scratch + 3ull * MROWS * DM)

// bf16 scratch offsets (elements; MROWS*DM = 4M, DM*DM = 1M)
#define BF_XHI  0ull
#define BF_XLO  (1ull * MROWS * DM)
#define BF_WT   (2ull * MROWS * DM)                       // 8 x DM*DM
#define BF_AHI  (BF_WT + 8ull * DM * DM)
#define BF_ALO  (BF_AHI + 1ull * MROWS * DM)
#define BF_QHI  (BF_ALO + 1ull * MROWS * DM)
#define BF_QLO  (BF_QHI + 1ull * MROWS * DM)
#define BF_KHI  (BF_QLO + 1ull * MROWS * DM)
#define BF_KLO  (BF_KHI + 1ull * MROWS * DM)
#define BF_VTHI (BF_KLO + 1ull * MROWS * DM)
#define BF_VTLO (BF_VTHI + 1ull * MROWS * DM)
__device__ __nv_bfloat16 g_bf[BF_VTLO + 1ull * MROWS * DM];

// ---------------------------------------------------------------------------
// Helpers (sm_100-safe: cp.async, ldmatrix, mma.sync only)
// ---------------------------------------------------------------------------
__device__ __forceinline__ uint32_t smem_u32(const void* p) {
    uint32_t a;
    asm("{ .reg .u64 t; cvta.to.shared.u64 t, %1; cvt.u32.u64 %0, t; }"
        : "=r"(a) : "l"(p));
    return a;
}

__device__ __forceinline__ uint32_t sw64(uint32_t off) {
    return off ^ ((off >> 3) & 0x30);
}
__device__ __forceinline__ uint32_t sw128(uint32_t off) {
    return off ^ ((off >> 3) & 0x70);
}

__device__ __forceinline__ void ldm_x4(uint32_t* r, uint32_t addr) {
    asm volatile("ldmatrix.sync.aligned.m8n8.x4.shared.b16 {%0,%1,%2,%3}, [%4];"
                 : "=r"(r[0]), "=r"(r[1]), "=r"(r[2]), "=r"(r[3]) : "r"(addr));
}
__device__ __forceinline__ void ldm_x2(uint32_t* r, uint32_t addr) {
    asm volatile("ldmatrix.sync.aligned.m8n8.x2.shared.b16 {%0,%1}, [%2];"
                 : "=r"(r[0]), "=r"(r[1]) : "r"(addr));
}

__device__ __forceinline__ void mma_bf16(float* d, const uint32_t* a,
                                         const uint32_t* b) {
    asm volatile(
        "mma.sync.aligned.m16n8k16.row.col.f32.bf16.bf16.f32 "
        "{%0,%1,%2,%3}, {%4,%5,%6,%7}, {%8,%9}, {%0,%1,%2,%3};"
        : "+f"(d[0]), "+f"(d[1]), "+f"(d[2]), "+f"(d[3])
        : "r"(a[0]), "r"(a[1]), "r"(a[2]), "r"(a[3]), "r"(b[0]), "r"(b[1]));
}

__device__ __forceinline__ void cp_async16(uint32_t dst, const void* src) {
    asm volatile("cp.async.cg.shared.global [%0], [%1], 16;"
                 :: "r"(dst), "l"(src));
}
#define CP_COMMIT() asm volatile("cp.async.commit_group;" ::: "memory")
#define CP_WAIT(n)  asm volatile("cp.async.wait_group %0;" :: "n"(n) : "memory")

__device__ __forceinline__ uint32_t packbf2(float a, float b) {
    __nv_bfloat162 t = __floats2bfloat162_rn(a, b);
    return *(uint32_t*)&t;
}

// ---------------------------------------------------------------------------
// Prep: fp32 -> (bf16 hi, bf16 lo) split, 4 elems/thread
// ---------------------------------------------------------------------------
__global__ __launch_bounds__(256) void split_kernel(
    const float* __restrict__ src, __nv_bfloat16* __restrict__ hi,
    __nv_bfloat16* __restrict__ lo)
{
    size_t i = (size_t)(blockIdx.x * 256 + threadIdx.x) * 4;
    float4 v = *(const float4*)(src + i);
    __nv_bfloat16 h0 = __float2bfloat16_rn(v.x);
    __nv_bfloat16 h1 = __float2bfloat16_rn(v.y);
    __nv_bfloat16 h2 = __float2bfloat16_rn(v.z);
    __nv_bfloat16 h3 = __float2bfloat16_rn(v.w);
    __nv_bfloat16 l0 = __float2bfloat16_rn(v.x - __bfloat162float(h0));
    __nv_bfloat16 l1 = __float2bfloat16_rn(v.y - __bfloat162float(h1));
    __nv_bfloat16 l2 = __float2bfloat16_rn(v.z - __bfloat162float(h2));
    __nv_bfloat16 l3 = __float2bfloat16_rn(v.w - __bfloat162float(h3));
    ((__nv_bfloat162*)(hi + i))[0] = __nv_bfloat162(h0, h1);
    ((__nv_bfloat162*)(hi + i))[1] = __nv_bfloat162(h2, h3);
    ((__nv_bfloat162*)(lo + i))[0] = __nv_bfloat162(l0, l1);
    ((__nv_bfloat162*)(lo + i))[1] = __nv_bfloat162(l2, l3);
}

// ---------------------------------------------------------------------------
// Prep: transpose + split the 4 weight matrices W[k][n] -> Wt_hi/lo[n][k]
// ---------------------------------------------------------------------------
__global__ __launch_bounds__(256) void wsplit_kernel(
    const float* __restrict__ W0, const float* __restrict__ W1,
    const float* __restrict__ W2, const float* __restrict__ W3)
{
    __shared__ float t[32][33];
    const float* W = (blockIdx.z == 0) ? W0 : (blockIdx.z == 1) ? W1
                   : (blockIdx.z == 2) ? W2 : W3;
    __nv_bfloat16* whi = g_bf + BF_WT + (size_t)(2 * blockIdx.z) * DM * DM;
    __nv_bfloat16* wlo = whi + (size_t)DM * DM;
    int tx = threadIdx.x, ty = threadIdx.y;
    int n = blockIdx.x * 32 + tx;
#pragma unroll
    for (int i = 0; i < 32; i += 8)
        t[ty + i][tx] = W[(size_t)(blockIdx.y * 32 + ty + i) * DM + n];
    __syncthreads();
#pragma unroll
    for (int i = 0; i < 32; i += 8) {
        float v = t[tx][ty + i];
        __nv_bfloat16 h = __float2bfloat16_rn(v);
        __nv_bfloat16 l = __float2bfloat16_rn(v - __bfloat162float(h));
        size_t o = (size_t)(blockIdx.x * 32 + ty + i) * DM + blockIdx.y * 32 + tx;
        whi[o] = h;
        wlo[o] = l;
    }
}

// ---------------------------------------------------------------------------
// mma.sync bf16-split GEMM (proven; now 2 CTAs/SM via launch_bounds)
// ---------------------------------------------------------------------------
#define KCH 32
#define STG_T 8192
#define STG_B (4 * STG_T)
#define MM_SMEM (2 * STG_B + 1024)

__global__ __launch_bounds__(256, 2) void mm_gemm(
    const __nv_bfloat16* __restrict__ Ahi, const __nv_bfloat16* __restrict__ Alo,
    const __nv_bfloat16* __restrict__ Bhi, const __nv_bfloat16* __restrict__ Blo,
    const float* __restrict__ bias, float* __restrict__ C)
{
    extern __shared__ char smraw[];
    const uint32_t sbase = (smem_u32(smraw) + 1023) & ~1023u;

    const int tid  = threadIdx.x;
    const int wid  = tid >> 5, lane = tid & 31;
    const int m0   = blockIdx.y * 128, n0 = blockIdx.x * 128;
    const int wm   = (wid >> 2) * 64, wn = (wid & 3) * 32;

    float acc[4][4][4];
#pragma unroll
    for (int i = 0; i < 4; i++)
#pragma unroll
        for (int j = 0; j < 4; j++)
#pragma unroll
            for (int r = 0; r < 4; r++) acc[i][j][r] = 0.f;

    auto load_stage = [&](int kt, int buf) {
        const uint32_t bb = sbase + buf * STG_B;
#pragma unroll
        for (int it = 0; it < 8; it++) {
            int i = it * 256 + tid;
            int tile = i >> 9, idx = i & 511;
            int r = idx >> 2, c = idx & 3;
            uint32_t dst = bb + tile * STG_T + sw64((uint32_t)(r * 64 + c * 16));
            size_t off = (tile < 2)
                ? (size_t)(m0 + r) * DM + kt * KCH + c * 8
                : (size_t)(n0 + r) * DM + kt * KCH + c * 8;
            const __nv_bfloat16* src =
                (tile == 0) ? Ahi + off : (tile == 1) ? Alo + off
              : (tile == 2) ? Bhi + off : Blo + off;
            cp_async16(dst, src);
        }
    };

    load_stage(0, 0);
    CP_COMMIT();

    for (int kt = 0; kt < DM / KCH; kt++) {
        const int buf = kt & 1;
        if (kt < DM / KCH - 1) {
            load_stage(kt + 1, buf ^ 1);
            CP_COMMIT();
            CP_WAIT(1);
        } else {
            CP_WAIT(0);
        }
        __syncthreads();

        const uint32_t bb = sbase + buf * STG_B;
#pragma unroll
        for (int ks = 0; ks < 2; ks++) {
            uint32_t ah[4][4], al[4][4];
#pragma unroll
            for (int mt = 0; mt < 4; mt++) {
                int row = wm + mt * 16 + (lane & 15);
                int c = ks * 2 + (lane >> 4);
                uint32_t so = sw64((uint32_t)(row * 64 + c * 16));
                ldm_x4(ah[mt], bb + 0 * STG_T + so);
                ldm_x4(al[mt], bb + 1 * STG_T + so);
            }
            uint32_t bh[4][2], bl[4][2];
#pragma unroll
            for (int nt = 0; nt < 4; nt++) {
                int row = wn + nt * 8 + (lane & 7);
                int c = ks * 2 + ((lane >> 3) & 1);
                uint32_t so = sw64((uint32_t)(row * 64 + c * 16));
                ldm_x2(bh[nt], bb + 2 * STG_T + so);
                ldm_x2(bl[nt], bb + 3 * STG_T + so);
            }
#pragma unroll
            for (int mt = 0; mt < 4; mt++)
#pragma unroll
                for (int nt = 0; nt < 4; nt++) {
                    mma_bf16(acc[mt][nt], ah[mt], bh[nt]);
                    mma_bf16(acc[mt][nt], ah[mt], bl[nt]);
                    mma_bf16(acc[mt][nt], al[mt], bh[nt]);
                }
        }
        __syncthreads();
    }

    const int g = lane >> 2, t = lane & 3;
#pragma unroll
    for (int mt = 0; mt < 4; mt++) {
        int r0 = m0 + wm + mt * 16 + g;
#pragma unroll
        for (int nt = 0; nt < 4; nt++) {
            int col = n0 + wn + nt * 8 + t * 2;
            float2 bv = *(const float2*)&bias[col];
            float2 o0, o1;
            o0.x = acc[mt][nt][0] + bv.x;
            o0.y = acc[mt][nt][1] + bv.y;
            o1.x = acc[mt][nt][2] + bv.x;
            o1.y = acc[mt][nt][3] + bv.y;
            *(float2*)&C[(size_t)r0 * DM + col] = o0;
            *(float2*)&C[(size_t)(r0 + 8) * DM + col] = o1;
        }
    }
}

// ---------------------------------------------------------------------------
// RoPE + bf16 hi/lo split. Reads fp32 g_Q/g_K, writes Qhi/Qlo/Khi/Klo
// ([b*S+s][1024] bf16 layout). Q additionally pre-scaled by 1/sqrt(64).
// ---------------------------------------------------------------------------
__global__ __launch_bounds__(256) void rope_split_kernel()
{
    int tid = blockIdx.x * blockDim.x + threadIdx.x;   // 0 .. 2^22-1
    int j  = tid & 31;
    int s  = (tid >> 5) & (SQ - 1);
    int bh = (tid >> 16) & 31;
    int sel = (tid >> 21) & 1;                         // 0=Q, 1=K
    int b = bh >> 4, h = bh & 15;

    size_t row = (size_t)(b * SQ + s) * DM + h * DKH;
    const float* base = (sel ? g_K : g_Q) + row;
    __nv_bfloat16* ohi = g_bf + (sel ? BF_KHI : BF_QHI) + row;
    __nv_bfloat16* olo = g_bf + (sel ? BF_KLO : BF_QLO) + row;

    float invf = (float)pow(10000.0, -(double)j / 32.0);
    float ang = (float)s * invf;
    float sn, c;
    sincosf(ang, &sn, &c);
    float x1 = base[j], x2 = base[j + 32];
    float r1 = x1 * c - x2 * sn;
    float r2 = x1 * sn + x2 * c;
    if (!sel) { r1 *= 0.125f; r2 *= 0.125f; }
    __nv_bfloat16 h1 = __float2bfloat16_rn(r1);
    __nv_bfloat16 h2 = __float2bfloat16_rn(r2);
    ohi[j]      = h1;
    ohi[j + 32] = h2;
    olo[j]      = __float2bfloat16_rn(r1 - __bfloat162float(h1));
    olo[j + 32] = __float2bfloat16_rn(r2 - __bfloat162float(h2));
}

// ---------------------------------------------------------------------------
// V transpose + split: g_V fp32 [b*S+s][h*64+d] -> Vt hi/lo [(bh*64+d)][s]
// ---------------------------------------------------------------------------
__global__ __launch_bounds__(256) void vt_split_kernel()
{
    __shared__ float t[32][33];
    int tx = threadIdx.x, ty = threadIdx.y;
    int bh = blockIdx.z, b = bh >> 4, h = bh & 15;
    int s0 = blockIdx.x * 32, d0 = blockIdx.y * 32;
#pragma unroll
    for (int i = 0; i < 32; i += 8)
        t[ty + i][tx] = g_V[(size_t)(b * SQ + s0 + ty + i) * DM + h * DKH + d0 + tx];
    __syncthreads();
#pragma unroll
    for (int i = 0; i < 32; i += 8) {
        float v = t[tx][ty + i];
        __nv_bfloat16 hv = __float2bfloat16_rn(v);
        size_t o = (size_t)(bh * DKH + d0 + ty + i) * SQ + s0 + tx;
        g_bf[BF_VTHI + o] = hv;
        g_bf[BF_VTLO + o] = __float2bfloat16_rn(v - __bfloat162float(hv));
    }
}

// ---------------------------------------------------------------------------
// Tensor-core flash attention v2: all operands pre-split bf16 in GMEM;
// cp.async double-buffered K/Vt stages (mm_gemm pipeline pattern).
// Grid (SQ/128, NB*NH), 256 threads = 8 warps; warp = one m16 q-band.
// ---------------------------------------------------------------------------
#define FS_QH 0
#define FS_QL 16384
#define FS_ST 32768            // stage base; per stage: KH,KL,VH,VL (8KB each)
#define FS_STB 32768           // stage size
#define FA3_SMEM (FS_ST + 2 * FS_STB + 1024)

__global__ __launch_bounds__(256, 2) void flash_tc()
{
    extern __shared__ char smraw[];
    const uint32_t sb = (smem_u32(smraw) + 1023) & ~1023u;

    const int tid = threadIdx.x;
    const int wid = tid >> 5, lane = tid & 31;
    const int bh = blockIdx.y, b = bh >> 4, h = bh & 15;
    const int q0 = blockIdx.x * 128;

    const __nv_bfloat16* Qh = g_bf + BF_QHI + (size_t)(b * SQ + q0) * DM + h * DKH;
    const __nv_bfloat16* Ql = g_bf + BF_QLO + (size_t)(b * SQ + q0) * DM + h * DKH;
    const __nv_bfloat16* Kh = g_bf + BF_KHI + (size_t)(b * SQ) * DM + h * DKH;
    const __nv_bfloat16* Kl = g_bf + BF_KLO + (size_t)(b * SQ) * DM + h * DKH;
    const __nv_bfloat16* Vh = g_bf + BF_VTHI + (size_t)(bh * DKH) * SQ;
    const __nv_bfloat16* Vl = g_bf + BF_VTLO + (size_t)(bh * DKH) * SQ;

    // ---- Q tile: cp.async 128x64 hi/lo (16KB each) ----
#pragma unroll
    for (int it = 0; it < 8; it++) {
        int i = it * 256 + tid;            // 0..2047
        int arr = i >> 10, idx = i & 1023;
        int row = idx >> 3, c8 = idx & 7;
        const __nv_bfloat16* src = (arr ? Ql : Qh) + (size_t)row * DM + c8 * 8;
        uint32_t dst = sb + (arr ? FS_QL : FS_QH)
                     + sw128((uint32_t)(row * 128 + c8 * 16));
        cp_async16(dst, src);
    }
    CP_COMMIT();

    // ---- stage loader: K hi/lo (64x64) + Vt hi/lo (64x64), 8KB each ----
    auto load_stage = [&](int ktile, int buf) {
        const uint32_t bb = sb + FS_ST + buf * FS_STB;
#pragma unroll
        for (int it = 0; it < 8; it++) {
            int i = it * 256 + tid;        // 0..2047
            int tile = i >> 9, idx = i & 511;
            int row = idx >> 3, c8 = idx & 7;
            const __nv_bfloat16* src;
            if (tile < 2) {
                src = (tile ? Kl : Kh)
                    + (size_t)(ktile * 64 + row) * DM + c8 * 8;
            } else {
                src = ((tile == 3) ? Vl : Vh)
                    + (size_t)row * SQ + ktile * 64 + c8 * 8;
            }
            uint32_t dst = bb + (tile << 13)
                         + sw128((uint32_t)(row * 128 + c8 * 16));
            cp_async16(dst, src);
        }
    };

    load_stage(0, 0);
    CP_COMMIT();
    CP_WAIT(1);                // Q arrived
    __syncthreads();

    // ---- Q fragments (held in regs) ----
    uint32_t qh[4][4], ql[4][4];
#pragma unroll
    for (int kt = 0; kt < 4; kt++) {
        int row = wid * 16 + (lane & 15);
        uint32_t so = sw128((uint32_t)(row * 128 + kt * 32 + (lane >> 4) * 16));
        ldm_x4(qh[kt], sb + FS_QH + so);
        ldm_x4(ql[kt], sb + FS_QL + so);
    }

    float m_i[2] = {-1e30f, -1e30f};
    float l_i[2] = {0.f, 0.f};
    float o[8][4];
#pragma unroll
    for (int nt = 0; nt < 8; nt++)
#pragma unroll
        for (int r = 0; r < 4; r++) o[nt][r] = 0.f;

    for (int ktile = 0; ktile < SQ / 64; ktile++) {
        const int buf = ktile & 1;
        if (ktile < SQ / 64 - 1) {
            load_stage(ktile + 1, buf ^ 1);
            CP_COMMIT();
            CP_WAIT(1);
        } else {
            CP_WAIT(0);
        }
        __syncthreads();

        const uint32_t bb = sb + FS_ST + buf * FS_STB;
        const uint32_t KH = bb, KL = bb + 8192, VH = bb + 16384, VL = bb + 24576;

        // ---- S = Q K^T (3-MMA split) ----
        float sacc[8][4];
#pragma unroll
        for (int nt = 0; nt < 8; nt++)
#pragma unroll
            for (int r = 0; r < 4; r++) sacc[nt][r] = 0.f;

#pragma unroll
        for (int kt = 0; kt < 4; kt++) {
            uint32_t bhf[8][2], blf[8][2];
#pragma unroll
            for (int nt = 0; nt < 8; nt++) {
                int row = nt * 8 + (lane & 7);
                uint32_t so = sw128((uint32_t)(row * 128 + kt * 32
                                               + ((lane >> 3) & 1) * 16));
                ldm_x2(bhf[nt], KH + so);
                ldm_x2(blf[nt], KL + so);
            }
#pragma unroll
            for (int nt = 0; nt < 8; nt++) {
                mma_bf16(sacc[nt], qh[kt], bhf[nt]);
                mma_bf16(sacc[nt], qh[kt], blf[nt]);
                mma_bf16(sacc[nt], ql[kt], bhf[nt]);
            }
        }

        // ---- online softmax (rows lane>>2 and +8) ----
        float mx0 = -1e30f, mx1 = -1e30f;
#pragma unroll
        for (int nt = 0; nt < 8; nt++) {
            mx0 = fmaxf(mx0, fmaxf(sacc[nt][0], sacc[nt][1]));
            mx1 = fmaxf(mx1, fmaxf(sacc[nt][2], sacc[nt][3]));
        }
        mx0 = fmaxf(mx0, __shfl_xor_sync(0xffffffffu, mx0, 1));
        mx0 = fmaxf(mx0, __shfl_xor_sync(0xffffffffu, mx0, 2));
        mx1 = fmaxf(mx1, __shfl_xor_sync(0xffffffffu, mx1, 1));
        mx1 = fmaxf(mx1, __shfl_xor_sync(0xffffffffu, mx1, 2));
        float mn0 = fmaxf(m_i[0], mx0), mn1 = fmaxf(m_i[1], mx1);
        float al0 = __expf(m_i[0] - mn0), al1 = __expf(m_i[1] - mn1);
        float rs0 = 0.f, rs1 = 0.f;
#pragma unroll
        for (int nt = 0; nt < 8; nt++) {
            sacc[nt][0] = __expf(sacc[nt][0] - mn0);
            sacc[nt][1] = __expf(sacc[nt][1] - mn0);
            sacc[nt][2] = __expf(sacc[nt][2] - mn1);
            sacc[nt][3] = __expf(sacc[nt][3] - mn1);
            rs0 += sacc[nt][0] + sacc[nt][1];
            rs1 += sacc[nt][2] + sacc[nt][3];
        }
        rs0 += __shfl_xor_sync(0xffffffffu, rs0, 1);
        rs0 += __shfl_xor_sync(0xffffffffu, rs0, 2);
        rs1 += __shfl_xor_sync(0xffffffffu, rs1, 1);
        rs1 += __shfl_xor_sync(0xffffffffu, rs1, 2);
        l_i[0] = l_i[0] * al0 + rs0;
        l_i[1] = l_i[1] * al1 + rs1;
        m_i[0] = mn0; m_i[1] = mn1;
#pragma unroll
        for (int nt = 0; nt < 8; nt++) {
            o[nt][0] *= al0; o[nt][1] *= al0;
            o[nt][2] *= al1; o[nt][3] *= al1;
        }

        // ---- P -> bf16 hi/lo A-frags; O += P Vt (3-MMA split) ----
#pragma unroll
        for (int t = 0; t < 4; t++) {
            float p00 = sacc[2 * t][0], p01 = sacc[2 * t][1];
            float p02 = sacc[2 * t][2], p03 = sacc[2 * t][3];
            float p10 = sacc[2 * t + 1][0], p11 = sacc[2 * t + 1][1];
            float p12 = sacc[2 * t + 1][2], p13 = sacc[2 * t + 1][3];
            float h00 = __bfloat162float(__float2bfloat16_rn(p00));
            float h01 = __bfloat162float(__float2bfloat16_rn(p01));
            float h02 = __bfloat162float(__float2bfloat16_rn(p02));
            float h03 = __bfloat162float(__float2bfloat16_rn(p03));
            float h10 = __bfloat162float(__float2bfloat16_rn(p10));
            float h11 = __bfloat162float(__float2bfloat16_rn(p11));
            float h12 = __bfloat162float(__float2bfloat16_rn(p12));
            float h13 = __bfloat162float(__float2bfloat16_rn(p13));
            uint32_t ahf[4], alf[4];
            ahf[0] = packbf2(h00, h01); ahf[1] = packbf2(h02, h03);
            ahf[2] = packbf2(h10, h11); ahf[3] = packbf2(h12, h13);
            alf[0] = packbf2(p00 - h00, p01 - h01);
            alf[1] = packbf2(p02 - h02, p03 - h03);
            alf[2] = packbf2(p10 - h10, p11 - h11);
            alf[3] = packbf2(p12 - h12, p13 - h13);
#pragma unroll
            for (int nt = 0; nt < 8; nt++) {
                uint32_t vh[2], vl[2];
                int row = nt * 8 + (lane & 7);
                uint32_t so = sw128((uint32_t)(row * 128 + t * 32
                                               + ((lane >> 3) & 1) * 16));
                ldm_x2(vh, VH + so);
                ldm_x2(vl, VL + so);
                mma_bf16(o[nt], ahf, vh);
                mma_bf16(o[nt], ahf, vl);
                mma_bf16(o[nt], alf, vh);
            }
        }
        __syncthreads();
    }

    // ---- epilogue: divide by l, store to g_A ----
    float inv0 = 1.f / l_i[0], inv1 = 1.f / l_i[1];
    int r0 = q0 + wid * 16 + (lane >> 2);
    float* Ap = g_A + ((size_t)(b * SQ)) * DM + h * DKH;
#pragma unroll
    for (int nt = 0; nt < 8; nt++) {
        int col = nt * 8 + (lane & 3) * 2;
        float2 v0, v1;
        v0.x = o[nt][0] * inv0; v0.y = o[nt][1] * inv0;
        v1.x = o[nt][2] * inv1; v1.y = o[nt][3] * inv1;
        *(float2*)(Ap + (size_t)r0 * DM + col) = v0;
        *(float2*)(Ap + (size_t)(r0 + 8) * DM + col) = v1;
    }
}

// ---------------------------------------------------------------------------
extern "C" void kernel_launch(void* const* d_in, const int* in_sizes, int n_in,
                              void* d_out, int out_size)
{
    const float* x  = (const float*)d_in[0];
    const float* Wq = (const float*)d_in[1];
    const float* bq = (const float*)d_in[2];
    const float* Wk = (const float*)d_in[3];
    const float* bk = (const float*)d_in[4];
    const float* Wv = (const float*)d_in[5];
    const float* bv = (const float*)d_in[6];
    const float* Wo = (const float*)d_in[7];
    const float* bo = (const float*)d_in[8];
    float* out = (float*)d_out;

    __nv_bfloat16* bf = nullptr;
    cudaGetSymbolAddress((void**)&bf, g_bf);
    float* fs = nullptr;
    cudaGetSymbolAddress((void**)&fs, g_scratch);
    float* gQ = fs;
    float* gK = fs + 1ull * MROWS * DM;
    float* gV = fs + 2ull * MROWS * DM;
    float* gA = fs + 3ull * MROWS * DM;

    cudaFuncSetAttribute(mm_gemm,
                         cudaFuncAttributeMaxDynamicSharedMemorySize, MM_SMEM);
    cudaFuncSetAttribute(flash_tc,
                         cudaFuncAttributeMaxDynamicSharedMemorySize, FA3_SMEM);

    // 1) split x -> bf16 hi/lo; transpose+split the 4 weights
    split_kernel<<<MROWS * DM / 1024, 256>>>(x, bf + BF_XHI, bf + BF_XLO);
    wsplit_kernel<<<dim3(32, 32, 4), dim3(32, 8)>>>(Wq, Wk, Wv, Wo);

    // 2) Q/K/V projections (mma.sync bf16-split)
    mm_gemm<<<dim3(8, 32), 256, MM_SMEM>>>(
        bf + BF_XHI, bf + BF_XLO,
        bf + BF_WT + 0ull * DM * DM, bf + BF_WT + 1ull * DM * DM, bq, gQ);
    mm_gemm<<<dim3(8, 32), 256, MM_SMEM>>>(
        bf + BF_XHI, bf + BF_XLO,
        bf + BF_WT + 2ull * DM * DM, bf + BF_WT + 3ull * DM * DM, bk, gK);
    mm_gemm<<<dim3(8, 32), 256, MM_SMEM>>>(
        bf + BF_XHI, bf + BF_XLO,
        bf + BF_WT + 4ull * DM * DM, bf + BF_WT + 5ull * DM * DM, bv, gV);

    // 3) RoPE + split to bf16 (Q,K); V transpose + split
    rope_split_kernel<<<(1 << 22) / 256, 256>>>();
    vt_split_kernel<<<dim3(SQ / 32, 2, NB * NH), dim3(32, 8)>>>();

    // 4) Flash attention on tensor cores (cp.async pipelined)
    flash_tc<<<dim3(SQ / 128, NB * NH), 256, FA3_SMEM>>>();

    // 5) split attn output, output projection
    split_kernel<<<MROWS * DM / 1024, 256>>>(gA, bf + BF_AHI, bf + BF_ALO);
    mm_gemm<<<dim3(8, 32), 256, MM_SMEM>>>(
        bf + BF_AHI, bf + BF_ALO,
        bf + BF_WT + 6ull * DM * DM, bf + BF_WT + 7ull * DM * DM, bo, out);
}

// round 7
// speedup vs baseline: 3.3371x; 1.0513x over previous
#include <cuda_runtime.h>
#include <cuda_bf16.h>
#include <math.h>
#include <stdint.h>

#define SQ   2048
#define NB   2
#define NH   16
#define DKH  64
#define DM   1024
#define MROWS 4096   // NB*SQ

// ---------------------------------------------------------------------------
// Scratch (__device__ globals; allocation-free rule)
// ---------------------------------------------------------------------------
__device__ float g_scratch[4ull * MROWS * DM];           // Q,K,V,A fp32
#define g_Q (g_scratch)
#define g_K (g_scratch + 1ull * MROWS * DM)
#define g_V (g_scratch + 2ull * MROWS * DM)
#define g_A (g_scratch + 3ull * MROWS * DM)

__device__ float g_rope[SQ * 32 * 2];                    // cos,sin per (s,j)

// bf16 scratch offsets (elements; MROWS*DM = 4M, DM*DM = 1M)
#define BF_XHI  0ull
#define BF_XLO  (1ull * MROWS * DM)
#define BF_WT   (2ull * MROWS * DM)                       // 8 x DM*DM
#define BF_AHI  (BF_WT + 8ull * DM * DM)
#define BF_ALO  (BF_AHI + 1ull * MROWS * DM)
#define BF_QHI  (BF_ALO + 1ull * MROWS * DM)
#define BF_QLO  (BF_QHI + 1ull * MROWS * DM)
#define BF_KHI  (BF_QLO + 1ull * MROWS * DM)
#define BF_KLO  (BF_KHI + 1ull * MROWS * DM)
#define BF_VTHI (BF_KLO + 1ull * MROWS * DM)
#define BF_VTLO (BF_VTHI + 1ull * MROWS * DM)
__device__ __nv_bfloat16 g_bf[BF_VTLO + 1ull * MROWS * DM];

// ---------------------------------------------------------------------------
// Helpers (sm_100-safe: cp.async, ldmatrix, mma.sync only)
// ---------------------------------------------------------------------------
__device__ __forceinline__ uint32_t smem_u32(const void* p) {
    uint32_t a;
    asm("{ .reg .u64 t; cvta.to.shared.u64 t, %1; cvt.u32.u64 %0, t; }"
        : "=r"(a) : "l"(p));
    return a;
}

__device__ __forceinline__ uint32_t sw64(uint32_t off) {
    return off ^ ((off >> 3) & 0x30);
}
__device__ __forceinline__ uint32_t sw128(uint32_t off) {
    return off ^ ((off >> 3) & 0x70);
}

__device__ __forceinline__ void ldm_x4(uint32_t* r, uint32_t addr) {
    asm volatile("ldmatrix.sync.aligned.m8n8.x4.shared.b16 {%0,%1,%2,%3}, [%4];"
                 : "=r"(r[0]), "=r"(r[1]), "=r"(r[2]), "=r"(r[3]) : "r"(addr));
}
__device__ __forceinline__ void ldm_x2(uint32_t* r, uint32_t addr) {
    asm volatile("ldmatrix.sync.aligned.m8n8.x2.shared.b16 {%0,%1}, [%2];"
                 : "=r"(r[0]), "=r"(r[1]) : "r"(addr));
}

__device__ __forceinline__ void mma_bf16(float* d, const uint32_t* a,
                                         const uint32_t* b) {
    asm volatile(
        "mma.sync.aligned.m16n8k16.row.col.f32.bf16.bf16.f32 "
        "{%0,%1,%2,%3}, {%4,%5,%6,%7}, {%8,%9}, {%0,%1,%2,%3};"
        : "+f"(d[0]), "+f"(d[1]), "+f"(d[2]), "+f"(d[3])
        : "r"(a[0]), "r"(a[1]), "r"(a[2]), "r"(a[3]), "r"(b[0]), "r"(b[1]));
}

__device__ __forceinline__ void cp_async16(uint32_t dst, const void* src) {
    asm volatile("cp.async.cg.shared.global [%0], [%1], 16;"
                 :: "r"(dst), "l"(src));
}
#define CP_COMMIT() asm volatile("cp.async.commit_group;" ::: "memory")
#define CP_WAIT(n)  asm volatile("cp.async.wait_group %0;" :: "n"(n) : "memory")

__device__ __forceinline__ uint32_t packbf2(float a, float b) {
    __nv_bfloat162 t = __floats2bfloat162_rn(a, b);
    return *(uint32_t*)&t;
}

// ---------------------------------------------------------------------------
// Prep: fp32 -> (bf16 hi, bf16 lo) split, 4 elems/thread
// ---------------------------------------------------------------------------
__global__ __launch_bounds__(256) void split_kernel(
    const float* __restrict__ src, __nv_bfloat16* __restrict__ hi,
    __nv_bfloat16* __restrict__ lo)
{
    size_t i = (size_t)(blockIdx.x * 256 + threadIdx.x) * 4;
    float4 v = *(const float4*)(src + i);
    __nv_bfloat16 h0 = __float2bfloat16_rn(v.x);
    __nv_bfloat16 h1 = __float2bfloat16_rn(v.y);
    __nv_bfloat16 h2 = __float2bfloat16_rn(v.z);
    __nv_bfloat16 h3 = __float2bfloat16_rn(v.w);
    __nv_bfloat16 l0 = __float2bfloat16_rn(v.x - __bfloat162float(h0));
    __nv_bfloat16 l1 = __float2bfloat16_rn(v.y - __bfloat162float(h1));
    __nv_bfloat16 l2 = __float2bfloat16_rn(v.z - __bfloat162float(h2));
    __nv_bfloat16 l3 = __float2bfloat16_rn(v.w - __bfloat162float(h3));
    ((__nv_bfloat162*)(hi + i))[0] = __nv_bfloat162(h0, h1);
    ((__nv_bfloat162*)(hi + i))[1] = __nv_bfloat162(h2, h3);
    ((__nv_bfloat162*)(lo + i))[0] = __nv_bfloat162(l0, l1);
    ((__nv_bfloat162*)(lo + i))[1] = __nv_bfloat162(l2, l3);
}

// ---------------------------------------------------------------------------
// Prep: transpose + split the 4 weight matrices W[k][n] -> Wt_hi/lo[n][k]
// ---------------------------------------------------------------------------
__global__ __launch_bounds__(256) void wsplit_kernel(
    const float* __restrict__ W0, const float* __restrict__ W1,
    const float* __restrict__ W2, const float* __restrict__ W3)
{
    __shared__ float t[32][33];
    const float* W = (blockIdx.z == 0) ? W0 : (blockIdx.z == 1) ? W1
                   : (blockIdx.z == 2) ? W2 : W3;
    __nv_bfloat16* whi = g_bf + BF_WT + (size_t)(2 * blockIdx.z) * DM * DM;
    __nv_bfloat16* wlo = whi + (size_t)DM * DM;
    int tx = threadIdx.x, ty = threadIdx.y;
    int n = blockIdx.x * 32 + tx;
#pragma unroll
    for (int i = 0; i < 32; i += 8)
        t[ty + i][tx] = W[(size_t)(blockIdx.y * 32 + ty + i) * DM + n];
    __syncthreads();
#pragma unroll
    for (int i = 0; i < 32; i += 8) {
        float v = t[tx][ty + i];
        __nv_bfloat16 h = __float2bfloat16_rn(v);
        __nv_bfloat16 l = __float2bfloat16_rn(v - __bfloat162float(h));
        size_t o = (size_t)(blockIdx.x * 32 + ty + i) * DM + blockIdx.y * 32 + tx;
        whi[o] = h;
        wlo[o] = l;
    }
}

// ---------------------------------------------------------------------------
// RoPE cos/sin table: (s, j) -> g_rope[2*(s*32+j)] = {cos, sin}
// ---------------------------------------------------------------------------
__global__ __launch_bounds__(256) void rope_table_kernel()
{
    int i = blockIdx.x * 256 + threadIdx.x;   // 0 .. 65535
    int s = i >> 5, j = i & 31;
    float invf = (float)pow(10000.0, -(double)j / 32.0);
    float ang = (float)s * invf;
    float sn, c;
    sincosf(ang, &sn, &c);
    g_rope[2 * i]     = c;
    g_rope[2 * i + 1] = sn;
}

// ---------------------------------------------------------------------------
// mma.sync bf16-split GEMM: 3-stage cp.async pipeline, one sync per K-chunk.
// ---------------------------------------------------------------------------
#define KCH 32
#define NKT (DM / KCH)             // 32 chunks
#define STG_T 8192
#define STG_B (4 * STG_T)          // 32 KB per stage
#define MM_SMEM (3 * STG_B + 1024)

__global__ __launch_bounds__(256, 2) void mm_gemm(
    const __nv_bfloat16* __restrict__ Ahi, const __nv_bfloat16* __restrict__ Alo,
    const __nv_bfloat16* __restrict__ Bhi, const __nv_bfloat16* __restrict__ Blo,
    const float* __restrict__ bias, float* __restrict__ C)
{
    extern __shared__ char smraw[];
    const uint32_t sbase = (smem_u32(smraw) + 1023) & ~1023u;

    const int tid  = threadIdx.x;
    const int wid  = tid >> 5, lane = tid & 31;
    const int m0   = blockIdx.y * 128, n0 = blockIdx.x * 128;
    const int wm   = (wid >> 2) * 64, wn = (wid & 3) * 32;

    float acc[4][4][4];
#pragma unroll
    for (int i = 0; i < 4; i++)
#pragma unroll
        for (int j = 0; j < 4; j++)
#pragma unroll
            for (int r = 0; r < 4; r++) acc[i][j][r] = 0.f;

    auto load_stage = [&](int kt, int slot) {
        const uint32_t bb = sbase + slot * STG_B;
#pragma unroll
        for (int it = 0; it < 8; it++) {
            int i = it * 256 + tid;
            int tile = i >> 9, idx = i & 511;
            int r = idx >> 2, c = idx & 3;
            uint32_t dst = bb + tile * STG_T + sw64((uint32_t)(r * 64 + c * 16));
            size_t off = (tile < 2)
                ? (size_t)(m0 + r) * DM + kt * KCH + c * 8
                : (size_t)(n0 + r) * DM + kt * KCH + c * 8;
            const __nv_bfloat16* src =
                (tile == 0) ? Ahi + off : (tile == 1) ? Alo + off
              : (tile == 2) ? Bhi + off : Blo + off;
            cp_async16(dst, src);
        }
    };

    load_stage(0, 0); CP_COMMIT();
    load_stage(1, 1); CP_COMMIT();

    int slot = 0;
    for (int kt = 0; kt < NKT; kt++) {
        CP_WAIT(1);          // stage kt has landed ({kt, kt+1} were in flight)
        __syncthreads();     // visibility + slot (kt-1) fully consumed
        if (kt + 2 < NKT) {
            int ns = slot + 2; if (ns >= 3) ns -= 3;
            load_stage(kt + 2, ns);
            CP_COMMIT();
        } else {
            CP_COMMIT();     // keep group count in step for CP_WAIT(1)
        }

        const uint32_t bb = sbase + slot * STG_B;
#pragma unroll
        for (int ks = 0; ks < 2; ks++) {
            uint32_t ah[4][4], al[4][4];
#pragma unroll
            for (int mt = 0; mt < 4; mt++) {
                int row = wm + mt * 16 + (lane & 15);
                int c = ks * 2 + (lane >> 4);
                uint32_t so = sw64((uint32_t)(row * 64 + c * 16));
                ldm_x4(ah[mt], bb + 0 * STG_T + so);
                ldm_x4(al[mt], bb + 1 * STG_T + so);
            }
            uint32_t bh[4][2], bl[4][2];
#pragma unroll
            for (int nt = 0; nt < 4; nt++) {
                int row = wn + nt * 8 + (lane & 7);
                int c = ks * 2 + ((lane >> 3) & 1);
                uint32_t so = sw64((uint32_t)(row * 64 + c * 16));
                ldm_x2(bh[nt], bb + 2 * STG_T + so);
                ldm_x2(bl[nt], bb + 3 * STG_T + so);
            }
#pragma unroll
            for (int mt = 0; mt < 4; mt++)
#pragma unroll
                for (int nt = 0; nt < 4; nt++) {
                    mma_bf16(acc[mt][nt], ah[mt], bh[nt]);
                    mma_bf16(acc[mt][nt], ah[mt], bl[nt]);
                    mma_bf16(acc[mt][nt], al[mt], bh[nt]);
                }
        }
        if (++slot == 3) slot = 0;
    }

    const int g = lane >> 2, t = lane & 3;
#pragma unroll
    for (int mt = 0; mt < 4; mt++) {
        int r0 = m0 + wm + mt * 16 + g;
#pragma unroll
        for (int nt = 0; nt < 4; nt++) {
            int col = n0 + wn + nt * 8 + t * 2;
            float2 bv = *(const float2*)&bias[col];
            float2 o0, o1;
            o0.x = acc[mt][nt][0] + bv.x;
            o0.y = acc[mt][nt][1] + bv.y;
            o1.x = acc[mt][nt][2] + bv.x;
            o1.y = acc[mt][nt][3] + bv.y;
            *(float2*)&C[(size_t)r0 * DM + col] = o0;
            *(float2*)&C[(size_t)(r0 + 8) * DM + col] = o1;
        }
    }
}

// ---------------------------------------------------------------------------
// RoPE (table lookup) + bf16 hi/lo split. Q pre-scaled by 1/8.
// ---------------------------------------------------------------------------
__global__ __launch_bounds__(256) void rope_split_kernel()
{
    int tid = blockIdx.x * blockDim.x + threadIdx.x;   // 0 .. 2^22-1
    int j  = tid & 31;
    int s  = (tid >> 5) & (SQ - 1);
    int bh = (tid >> 16) & 31;
    int sel = (tid >> 21) & 1;                         // 0=Q, 1=K
    int b = bh >> 4, h = bh & 15;

    size_t row = (size_t)(b * SQ + s) * DM + h * DKH;
    const float* base = (sel ? g_K : g_Q) + row;
    __nv_bfloat16* ohi = g_bf + (sel ? BF_KHI : BF_QHI) + row;
    __nv_bfloat16* olo = g_bf + (sel ? BF_KLO : BF_QLO) + row;

    float2 cs = *(const float2*)&g_rope[2 * (s * 32 + j)];
    float x1 = base[j], x2 = base[j + 32];
    float r1 = x1 * cs.x - x2 * cs.y;
    float r2 = x1 * cs.y + x2 * cs.x;
    if (!sel) { r1 *= 0.125f; r2 *= 0.125f; }
    __nv_bfloat16 h1 = __float2bfloat16_rn(r1);
    __nv_bfloat16 h2 = __float2bfloat16_rn(r2);
    ohi[j]      = h1;
    ohi[j + 32] = h2;
    olo[j]      = __float2bfloat16_rn(r1 - __bfloat162float(h1));
    olo[j + 32] = __float2bfloat16_rn(r2 - __bfloat162float(h2));
}

// ---------------------------------------------------------------------------
// V transpose + split: g_V fp32 [b*S+s][h*64+d] -> Vt hi/lo [(bh*64+d)][s]
// ---------------------------------------------------------------------------
__global__ __launch_bounds__(256) void vt_split_kernel()
{
    __shared__ float t[32][33];
    int tx = threadIdx.x, ty = threadIdx.y;
    int bh = blockIdx.z, b = bh >> 4, h = bh & 15;
    int s0 = blockIdx.x * 32, d0 = blockIdx.y * 32;
#pragma unroll
    for (int i = 0; i < 32; i += 8)
        t[ty + i][tx] = g_V[(size_t)(b * SQ + s0 + ty + i) * DM + h * DKH + d0 + tx];
    __syncthreads();
#pragma unroll
    for (int i = 0; i < 32; i += 8) {
        float v = t[tx][ty + i];
        __nv_bfloat16 hv = __float2bfloat16_rn(v);
        size_t o = (size_t)(bh * DKH + d0 + ty + i) * SQ + s0 + tx;
        g_bf[BF_VTHI + o] = hv;
        g_bf[BF_VTLO + o] = __float2bfloat16_rn(v - __bfloat162float(hv));
    }
}

// ---------------------------------------------------------------------------
// Tensor-core flash attention (unchanged from R6; proven)
// ---------------------------------------------------------------------------
#define FS_QH 0
#define FS_QL 16384
#define FS_ST 32768
#define FS_STB 32768
#define FA3_SMEM (FS_ST + 2 * FS_STB + 1024)

__global__ __launch_bounds__(256, 2) void flash_tc()
{
    extern __shared__ char smraw[];
    const uint32_t sb = (smem_u32(smraw) + 1023) & ~1023u;

    const int tid = threadIdx.x;
    const int wid = tid >> 5, lane = tid & 31;
    const int bh = blockIdx.y, b = bh >> 4, h = bh & 15;
    const int q0 = blockIdx.x * 128;

    const __nv_bfloat16* Qh = g_bf + BF_QHI + (size_t)(b * SQ + q0) * DM + h * DKH;
    const __nv_bfloat16* Ql = g_bf + BF_QLO + (size_t)(b * SQ + q0) * DM + h * DKH;
    const __nv_bfloat16* Kh = g_bf + BF_KHI + (size_t)(b * SQ) * DM + h * DKH;
    const __nv_bfloat16* Kl = g_bf + BF_KLO + (size_t)(b * SQ) * DM + h * DKH;
    const __nv_bfloat16* Vh = g_bf + BF_VTHI + (size_t)(bh * DKH) * SQ;
    const __nv_bfloat16* Vl = g_bf + BF_VTLO + (size_t)(bh * DKH) * SQ;

#pragma unroll
    for (int it = 0; it < 8; it++) {
        int i = it * 256 + tid;            // 0..2047
        int arr = i >> 10, idx = i & 1023;
        int row = idx >> 3, c8 = idx & 7;
        const __nv_bfloat16* src = (arr ? Ql : Qh) + (size_t)row * DM + c8 * 8;
        uint32_t dst = sb + (arr ? FS_QL : FS_QH)
                     + sw128((uint32_t)(row * 128 + c8 * 16));
        cp_async16(dst, src);
    }
    CP_COMMIT();

    auto load_stage = [&](int ktile, int buf) {
        const uint32_t bb = sb + FS_ST + buf * FS_STB;
#pragma unroll
        for (int it = 0; it < 8; it++) {
            int i = it * 256 + tid;        // 0..2047
            int tile = i >> 9, idx = i & 511;
            int row = idx >> 3, c8 = idx & 7;
            const __nv_bfloat16* src;
            if (tile < 2) {
                src = (tile ? Kl : Kh)
                    + (size_t)(ktile * 64 + row) * DM + c8 * 8;
            } else {
                src = ((tile == 3) ? Vl : Vh)
                    + (size_t)row * SQ + ktile * 64 + c8 * 8;
            }
            uint32_t dst = bb + (tile << 13)
                         + sw128((uint32_t)(row * 128 + c8 * 16));
            cp_async16(dst, src);
        }
    };

    load_stage(0, 0);
    CP_COMMIT();
    CP_WAIT(1);                // Q arrived
    __syncthreads();

    uint32_t qh[4][4], ql[4][4];
#pragma unroll
    for (int kt = 0; kt < 4; kt++) {
        int row = wid * 16 + (lane & 15);
        uint32_t so = sw128((uint32_t)(row * 128 + kt * 32 + (lane >> 4) * 16));
        ldm_x4(qh[kt], sb + FS_QH + so);
        ldm_x4(ql[kt], sb + FS_QL + so);
    }

    float m_i[2] = {-1e30f, -1e30f};
    float l_i[2] = {0.f, 0.f};
    float o[8][4];
#pragma unroll
    for (int nt = 0; nt < 8; nt++)
#pragma unroll
        for (int r = 0; r < 4; r++) o[nt][r] = 0.f;

    for (int ktile = 0; ktile < SQ / 64; ktile++) {
        const int buf = ktile & 1;
        if (ktile < SQ / 64 - 1) {
            load_stage(ktile + 1, buf ^ 1);
            CP_COMMIT();
            CP_WAIT(1);
        } else {
            CP_WAIT(0);
        }
        __syncthreads();

        const uint32_t bb = sb + FS_ST + buf * FS_STB;
        const uint32_t KH = bb, KL = bb + 8192, VH = bb + 16384, VL = bb + 24576;

        float sacc[8][4];
#pragma unroll
        for (int nt = 0; nt < 8; nt++)
#pragma unroll
            for (int r = 0; r < 4; r++) sacc[nt][r] = 0.f;

#pragma unroll
        for (int kt = 0; kt < 4; kt++) {
            uint32_t bhf[8][2], blf[8][2];
#pragma unroll
            for (int nt = 0; nt < 8; nt++) {
                int row = nt * 8 + (lane & 7);
                uint32_t so = sw128((uint32_t)(row * 128 + kt * 32
                                               + ((lane >> 3) & 1) * 16));
                ldm_x2(bhf[nt], KH + so);
                ldm_x2(blf[nt], KL + so);
            }
#pragma unroll
            for (int nt = 0; nt < 8; nt++) {
                mma_bf16(sacc[nt], qh[kt], bhf[nt]);
                mma_bf16(sacc[nt], qh[kt], blf[nt]);
                mma_bf16(sacc[nt], ql[kt], bhf[nt]);
            }
        }

        float mx0 = -1e30f, mx1 = -1e30f;
#pragma unroll
        for (int nt = 0; nt < 8; nt++) {
            mx0 = fmaxf(mx0, fmaxf(sacc[nt][0], sacc[nt][1]));
            mx1 = fmaxf(mx1, fmaxf(sacc[nt][2], sacc[nt][3]));
        }
        mx0 = fmaxf(mx0, __shfl_xor_sync(0xffffffffu, mx0, 1));
        mx0 = fmaxf(mx0, __shfl_xor_sync(0xffffffffu, mx0, 2));
        mx1 = fmaxf(mx1, __shfl_xor_sync(0xffffffffu, mx1, 1));
        mx1 = fmaxf(mx1, __shfl_xor_sync(0xffffffffu, mx1, 2));
        float mn0 = fmaxf(m_i[0], mx0), mn1 = fmaxf(m_i[1], mx1);
        float al0 = __expf(m_i[0] - mn0), al1 = __expf(m_i[1] - mn1);
        float rs0 = 0.f, rs1 = 0.f;
#pragma unroll
        for (int nt = 0; nt < 8; nt++) {
            sacc[nt][0] = __expf(sacc[nt][0] - mn0);
            sacc[nt][1] = __expf(sacc[nt][1] - mn0);
            sacc[nt][2] = __expf(sacc[nt][2] - mn1);
            sacc[nt][3] = __expf(sacc[nt][3] - mn1);
            rs0 += sacc[nt][0] + sacc[nt][1];
            rs1 += sacc[nt][2] + sacc[nt][3];
        }
        rs0 += __shfl_xor_sync(0xffffffffu, rs0, 1);
        rs0 += __shfl_xor_sync(0xffffffffu, rs0, 2);
        rs1 += __shfl_xor_sync(0xffffffffu, rs1, 1);
        rs1 += __shfl_xor_sync(0xffffffffu, rs1, 2);
        l_i[0] = l_i[0] * al0 + rs0;
        l_i[1] = l_i[1] * al1 + rs1;
        m_i[0] = mn0; m_i[1] = mn1;
#pragma unroll
        for (int nt = 0; nt < 8; nt++) {
            o[nt][0] *= al0; o[nt][1] *= al0;
            o[nt][2] *= al1; o[nt][3] *= al1;
        }

#pragma unroll
        for (int t = 0; t < 4; t++) {
            float p00 = sacc[2 * t][0], p01 = sacc[2 * t][1];
            float p02 = sacc[2 * t][2], p03 = sacc[2 * t][3];
            float p10 = sacc[2 * t + 1][0], p11 = sacc[2 * t + 1][1];
            float p12 = sacc[2 * t + 1][2], p13 = sacc[2 * t + 1][3];
            float h00 = __bfloat162float(__float2bfloat16_rn(p00));
            float h01 = __bfloat162float(__float2bfloat16_rn(p01));
            float h02 = __bfloat162float(__float2bfloat16_rn(p02));
            float h03 = __bfloat162float(__float2bfloat16_rn(p03));
            float h10 = __bfloat162float(__float2bfloat16_rn(p10));
            float h11 = __bfloat162float(__float2bfloat16_rn(p11));
            float h12 = __bfloat162float(__float2bfloat16_rn(p12));
            float h13 = __bfloat162float(__float2bfloat16_rn(p13));
            uint32_t ahf[4], alf[4];
            ahf[0] = packbf2(h00, h01); ahf[1] = packbf2(h02, h03);
            ahf[2] = packbf2(h10, h11); ahf[3] = packbf2(h12, h13);
            alf[0] = packbf2(p00 - h00, p01 - h01);
            alf[1] = packbf2(p02 - h02, p03 - h03);
            alf[2] = packbf2(p10 - h10, p11 - h11);
            alf[3] = packbf2(p12 - h12, p13 - h13);
#pragma unroll
            for (int nt = 0; nt < 8; nt++) {
                uint32_t vh[2], vl[2];
                int row = nt * 8 + (lane & 7);
                uint32_t so = sw128((uint32_t)(row * 128 + t * 32
                                               + ((lane >> 3) & 1) * 16));
                ldm_x2(vh, VH + so);
                ldm_x2(vl, VL + so);
                mma_bf16(o[nt], ahf, vh);
                mma_bf16(o[nt], ahf, vl);
                mma_bf16(o[nt], alf, vh);
            }
        }
        __syncthreads();
    }

    float inv0 = 1.f / l_i[0], inv1 = 1.f / l_i[1];
    int r0 = q0 + wid * 16 + (lane >> 2);
    float* Ap = g_A + ((size_t)(b * SQ)) * DM + h * DKH;
#pragma unroll
    for (int nt = 0; nt < 8; nt++) {
        int col = nt * 8 + (lane & 3) * 2;
        float2 v0, v1;
        v0.x = o[nt][0] * inv0; v0.y = o[nt][1] * inv0;
        v1.x = o[nt][2] * inv1; v1.y = o[nt][3] * inv1;
        *(float2*)(Ap + (size_t)r0 * DM + col) = v0;
        *(float2*)(Ap + (size_t)(r0 + 8) * DM + col) = v1;
    }
}

// ---------------------------------------------------------------------------
extern "C" void kernel_launch(void* const* d_in, const int* in_sizes, int n_in,
                              void* d_out, int out_size)
{
    const float* x  = (const float*)d_in[0];
    const float* Wq = (const float*)d_in[1];
    const float* bq = (const float*)d_in[2];
    const float* Wk = (const float*)d_in[3];
    const float* bk = (const float*)d_in[4];
    const float* Wv = (const float*)d_in[5];
    const float* bv = (const float*)d_in[6];
    const float* Wo = (const float*)d_in[7];
    const float* bo = (const float*)d_in[8];
    float* out = (float*)d_out;

    __nv_bfloat16* bf = nullptr;
    cudaGetSymbolAddress((void**)&bf, g_bf);
    float* fs = nullptr;
    cudaGetSymbolAddress((void**)&fs, g_scratch);
    float* gQ = fs;
    float* gK = fs + 1ull * MROWS * DM;
    float* gV = fs + 2ull * MROWS * DM;
    float* gA = fs + 3ull * MROWS * DM;

    cudaFuncSetAttribute(mm_gemm,
                         cudaFuncAttributeMaxDynamicSharedMemorySize, MM_SMEM);
    cudaFuncSetAttribute(flash_tc,
                         cudaFuncAttributeMaxDynamicSharedMemorySize, FA3_SMEM);

    // 1) prep: rope table (early, independent), x split, weight transpose+split
    rope_table_kernel<<<SQ * 32 / 256, 256>>>();
    split_kernel<<<MROWS * DM / 1024, 256>>>(x, bf + BF_XHI, bf + BF_XLO);
    wsplit_kernel<<<dim3(32, 32, 4), dim3(32, 8)>>>(Wq, Wk, Wv, Wo);

    // 2) Q/K/V projections (mma.sync bf16-split, 3-stage pipeline)
    mm_gemm<<<dim3(8, 32), 256, MM_SMEM>>>(
        bf + BF_XHI, bf + BF_XLO,
        bf + BF_WT + 0ull * DM * DM, bf + BF_WT + 1ull * DM * DM, bq, gQ);
    mm_gemm<<<dim3(8, 32), 256, MM_SMEM>>>(
        bf + BF_XHI, bf + BF_XLO,
        bf + BF_WT + 2ull * DM * DM, bf + BF_WT + 3ull * DM * DM, bk, gK);
    mm_gemm<<<dim3(8, 32), 256, MM_SMEM>>>(
        bf + BF_XHI, bf + BF_XLO,
        bf + BF_WT + 4ull * DM * DM, bf + BF_WT + 5ull * DM * DM, bv, gV);

    // 3) RoPE (table) + split to bf16 (Q,K); V transpose + split
    rope_split_kernel<<<(1 << 22) / 256, 256>>>();
    vt_split_kernel<<<dim3(SQ / 32, 2, NB * NH), dim3(32, 8)>>>();

    // 4) Flash attention on tensor cores (cp.async pipelined)
    flash_tc<<<dim3(SQ / 128, NB * NH), 256, FA3_SMEM>>>();

    // 5) split attn output, output projection
    split_kernel<<<MROWS * DM / 1024, 256>>>(gA, bf + BF_AHI, bf + BF_ALO);
    mm_gemm<<<dim3(8, 32), 256, MM_SMEM>>>(
        bf + BF_AHI, bf + BF_ALO,
        bf + BF_WT + 6ull * DM * DM, bf + BF_WT + 7ull * DM * DM, bo, out);
}